// round 2
// baseline (speedup 1.0000x reference)
#include <cuda_runtime.h>

// Problem constants
#define Bb    2
#define Tt    48
#define FQn   100
#define Dd    512
#define Hh    8
#define HDd   64
#define DFFd  2048
#define Ll    6
#define WSZw  8
#define NWw   6          // windows per batch item (T/WSZ)
#define NWIN  12         // B * NWw
#define Ss    800        // WSZ * FQ
#define HALFh 4          // ceil(WSZ/2)
#define NTOK  9600       // B*T*FQ
#define WHn   96         // NWIN * H

// Scratch (device globals: allocation-guard safe)
__device__ float g_x[NTOK * Dd];
__device__ float g_xw[NTOK * Dd];
__device__ float g_tmp[NTOK * Dd];
__device__ float g_attn[NTOK * Dd];
__device__ float g_qkv[NTOK * 3 * Dd];
__device__ float g_ffn[NTOK * DFFd];
__device__ float g_scores[(size_t)WHn * Ss * Ss];

// ---------------------------------------------------------------------------
// Generic NT GEMM: C[N,M] = A[N,K] @ W[M,K]^T + bias[M]   (all row-major)
// Tiles: 64x64, BK=16, 256 threads, 4x4 per thread. N,M assumed %64==0, K%16==0.
// grid = (M/64, N/64)
// ---------------------------------------------------------------------------
__global__ __launch_bounds__(256) void gemm_nt(
    const float* __restrict__ A, int lda,
    const float* __restrict__ W, int ldw,
    const float* __restrict__ bias,
    float* __restrict__ C, int ldc,
    int K, int relu)
{
    __shared__ float As[16][64];
    __shared__ float Ws[16][64];
    const int bm = blockIdx.y << 6;   // N dim
    const int bn = blockIdx.x << 6;   // M dim
    const int tid = threadIdx.x;
    const int tx = tid & 15, ty = tid >> 4;
    const int lrow = tid >> 2, lk = (tid & 3) << 2;
    float acc[4][4] = {};
    const float* Ap = A + (size_t)(bm + lrow) * lda + lk;
    const float* Wq = W + (size_t)(bn + lrow) * ldw + lk;
    for (int k0 = 0; k0 < K; k0 += 16) {
        float4 a4 = *(const float4*)(Ap + k0);
        float4 w4 = *(const float4*)(Wq + k0);
        As[lk + 0][lrow] = a4.x; As[lk + 1][lrow] = a4.y;
        As[lk + 2][lrow] = a4.z; As[lk + 3][lrow] = a4.w;
        Ws[lk + 0][lrow] = w4.x; Ws[lk + 1][lrow] = w4.y;
        Ws[lk + 2][lrow] = w4.z; Ws[lk + 3][lrow] = w4.w;
        __syncthreads();
        #pragma unroll
        for (int kk = 0; kk < 16; kk++) {
            float4 a = *(const float4*)(&As[kk][ty << 2]);
            float4 w = *(const float4*)(&Ws[kk][tx << 2]);
            float ar[4] = {a.x, a.y, a.z, a.w};
            float wr[4] = {w.x, w.y, w.z, w.w};
            #pragma unroll
            for (int i = 0; i < 4; i++)
                #pragma unroll
                for (int j = 0; j < 4; j++)
                    acc[i][j] += ar[i] * wr[j];
        }
        __syncthreads();
    }
    const int row = bm + (ty << 2);
    const int col = bn + (tx << 2);
    const float4 b4 = *(const float4*)(bias + col);
    #pragma unroll
    for (int i = 0; i < 4; i++) {
        float4 o4;
        o4.x = acc[i][0] + b4.x;
        o4.y = acc[i][1] + b4.y;
        o4.z = acc[i][2] + b4.z;
        o4.w = acc[i][3] + b4.w;
        if (relu) {
            o4.x = fmaxf(o4.x, 0.f); o4.y = fmaxf(o4.y, 0.f);
            o4.z = fmaxf(o4.z, 0.f); o4.w = fmaxf(o4.w, 0.f);
        }
        *(float4*)(C + (size_t)(row + i) * ldc + col) = o4;
    }
}

// ---------------------------------------------------------------------------
// Window gather with roll: xw[w*S+s] = x[token(w,s,shift)]
// One thread per float4; total NTOK*128 threads (exact multiple of 256).
// ---------------------------------------------------------------------------
__global__ __launch_bounds__(256) void gather_win(
    const float* __restrict__ x, float* __restrict__ xw, int shift)
{
    const int idx = blockIdx.x * 256 + threadIdx.x;
    const int row = idx >> 7;
    const int c = idx & 127;
    const int w = row / Ss, sidx = row % Ss;
    const int b = w / NWw, nw = w % NWw;
    const int tl = sidx / FQn, fq = sidx % FQn;
    int t = nw * WSZw + tl - shift;
    if (t < 0) t += Tt;
    const size_t n = (size_t)(b * Tt + t) * FQn + fq;
    ((float4*)xw)[(size_t)row * 128 + c] = ((const float4*)x)[n * 128 + c];
}

// ---------------------------------------------------------------------------
// Scores: S[wh, q, k] = (Q[q,:] . K[k,:]) * 0.125  (+ shift mask)
// grid = (13, 13, 96), 64x64 tile per block, hd=64 as 4 BK=16 steps.
// ---------------------------------------------------------------------------
__global__ __launch_bounds__(256) void attn_scores(
    const float* __restrict__ qkv, float* __restrict__ scores, int shifted)
{
    const int wh = blockIdx.z;
    const int w = wh >> 3, h = wh & 7;
    const int bq = blockIdx.y << 6, bk = blockIdx.x << 6;
    __shared__ float Qs[16][64];
    __shared__ float Ks[16][64];
    const int tid = threadIdx.x;
    const int tx = tid & 15, ty = tid >> 4;
    const int lrow = tid >> 2, lk = (tid & 3) << 2;
    float acc[4][4] = {};
    const float* base = qkv + (size_t)w * Ss * (3 * Dd) + h * HDd;
    const int qr = bq + lrow, kr = bk + lrow;
    const float* Qp = base + (size_t)qr * (3 * Dd);
    const float* Kp = base + Dd + (size_t)kr * (3 * Dd);
    for (int k0 = 0; k0 < HDd; k0 += 16) {
        float4 q4 = make_float4(0.f, 0.f, 0.f, 0.f);
        float4 k4 = make_float4(0.f, 0.f, 0.f, 0.f);
        if (qr < Ss) q4 = *(const float4*)(Qp + k0 + lk);
        if (kr < Ss) k4 = *(const float4*)(Kp + k0 + lk);
        Qs[lk + 0][lrow] = q4.x; Qs[lk + 1][lrow] = q4.y;
        Qs[lk + 2][lrow] = q4.z; Qs[lk + 3][lrow] = q4.w;
        Ks[lk + 0][lrow] = k4.x; Ks[lk + 1][lrow] = k4.y;
        Ks[lk + 2][lrow] = k4.z; Ks[lk + 3][lrow] = k4.w;
        __syncthreads();
        #pragma unroll
        for (int kk = 0; kk < 16; kk++) {
            float4 a = *(const float4*)(&Qs[kk][ty << 2]);
            float4 b4 = *(const float4*)(&Ks[kk][tx << 2]);
            float ar[4] = {a.x, a.y, a.z, a.w};
            float br[4] = {b4.x, b4.y, b4.z, b4.w};
            #pragma unroll
            for (int i = 0; i < 4; i++)
                #pragma unroll
                for (int j = 0; j < 4; j++)
                    acc[i][j] += ar[i] * br[j];
        }
        __syncthreads();
    }
    float* Cb = scores + (size_t)wh * Ss * Ss;
    const bool maskw = (shifted != 0) && ((w % NWw) == 0);
    #pragma unroll
    for (int i = 0; i < 4; i++) {
        const int q = bq + (ty << 2) + i;
        if (q >= Ss) continue;
        const int tq = q / FQn;
        #pragma unroll
        for (int j = 0; j < 4; j++) {
            const int k = bk + (tx << 2) + j;
            if (k >= Ss) continue;
            float v = acc[i][j] * 0.125f;
            if (maskw) {
                const int tk = k / FQn;
                if ((tq < HALFh) != (tk < HALFh)) v -= 1000.0f;
            }
            Cb[(size_t)q * Ss + k] = v;
        }
    }
}

// ---------------------------------------------------------------------------
// Row softmax over 800 entries; one block per row, values held in registers.
// grid = WHn * Ss
// ---------------------------------------------------------------------------
__global__ __launch_bounds__(256) void softmax_rows(float* __restrict__ scores)
{
    float* p = scores + (size_t)blockIdx.x * Ss;
    const int tid = threadIdx.x;
    float v[4];
    float lmax = -3.0e38f;
    #pragma unroll
    for (int i = 0; i < 4; i++) {
        const int idx = tid + (i << 8);
        v[i] = (idx < Ss) ? p[idx] : -3.0e38f;
        lmax = fmaxf(lmax, v[i]);
    }
    __shared__ float redm[8];
    __shared__ float reds[8];
    #pragma unroll
    for (int o = 16; o > 0; o >>= 1)
        lmax = fmaxf(lmax, __shfl_xor_sync(0xffffffffu, lmax, o));
    if ((tid & 31) == 0) redm[tid >> 5] = lmax;
    __syncthreads();
    const float m = fmaxf(fmaxf(fmaxf(redm[0], redm[1]), fmaxf(redm[2], redm[3])),
                          fmaxf(fmaxf(redm[4], redm[5]), fmaxf(redm[6], redm[7])));
    float lsum = 0.f;
    #pragma unroll
    for (int i = 0; i < 4; i++) {
        const int idx = tid + (i << 8);
        if (idx < Ss) { v[i] = __expf(v[i] - m); lsum += v[i]; }
    }
    #pragma unroll
    for (int o = 16; o > 0; o >>= 1)
        lsum += __shfl_xor_sync(0xffffffffu, lsum, o);
    if ((tid & 31) == 0) reds[tid >> 5] = lsum;
    __syncthreads();
    const float ssum = reds[0] + reds[1] + reds[2] + reds[3] +
                       reds[4] + reds[5] + reds[6] + reds[7];
    const float inv = 1.0f / ssum;
    #pragma unroll
    for (int i = 0; i < 4; i++) {
        const int idx = tid + (i << 8);
        if (idx < Ss) p[idx] = v[i] * inv;
    }
}

// ---------------------------------------------------------------------------
// O[wh, q, :] = A[wh, q, :] @ V[wh, :, :]   (A: 800x800, V: 800x64)
// grid = (13, 1, 96). Writes into attn[w*S+q, h*64 + d].
// ---------------------------------------------------------------------------
__global__ __launch_bounds__(256) void attn_av(
    const float* __restrict__ scores, const float* __restrict__ qkv,
    float* __restrict__ attn)
{
    const int wh = blockIdx.z;
    const int w = wh >> 3, h = wh & 7;
    const int bq = blockIdx.x << 6;
    __shared__ float As[16][64];   // [kk][q]
    __shared__ float Vs[16][64];   // [kk][d]
    const int tid = threadIdx.x;
    const int tx = tid & 15, ty = tid >> 4;
    const int lrow = tid >> 2, lk = (tid & 3) << 2;  // scores tile load
    const int vk = tid >> 4, vd = (tid & 15) << 2;   // V tile load
    float acc[4][4] = {};
    const float* Ab = scores + (size_t)wh * Ss * Ss;
    const float* Vb = qkv + (size_t)w * Ss * (3 * Dd) + 2 * Dd + h * HDd;
    const int q = bq + lrow;
    for (int k0 = 0; k0 < Ss; k0 += 16) {
        float4 a4 = make_float4(0.f, 0.f, 0.f, 0.f);
        if (q < Ss) a4 = *(const float4*)(Ab + (size_t)q * Ss + k0 + lk);
        As[lk + 0][lrow] = a4.x; As[lk + 1][lrow] = a4.y;
        As[lk + 2][lrow] = a4.z; As[lk + 3][lrow] = a4.w;
        *(float4*)(&Vs[vk][vd]) = *(const float4*)(Vb + (size_t)(k0 + vk) * (3 * Dd) + vd);
        __syncthreads();
        #pragma unroll
        for (int kk = 0; kk < 16; kk++) {
            float4 a = *(const float4*)(&As[kk][ty << 2]);
            float4 vv = *(const float4*)(&Vs[kk][tx << 2]);
            float ar[4] = {a.x, a.y, a.z, a.w};
            float vr[4] = {vv.x, vv.y, vv.z, vv.w};
            #pragma unroll
            for (int i = 0; i < 4; i++)
                #pragma unroll
                for (int j = 0; j < 4; j++)
                    acc[i][j] += ar[i] * vr[j];
        }
        __syncthreads();
    }
    #pragma unroll
    for (int i = 0; i < 4; i++) {
        const int qq = bq + (ty << 2) + i;
        if (qq >= Ss) continue;
        float4 o4 = make_float4(acc[i][0], acc[i][1], acc[i][2], acc[i][3]);
        *(float4*)(attn + (size_t)(w * Ss + qq) * Dd + h * HDd + (tx << 2)) = o4;
    }
}

// ---------------------------------------------------------------------------
// dst[row'] = LayerNorm(xa[row] + xb[row]) * gs + gb
// scatter!=0: row is windowed index, dst row is un-rolled token index.
// One block per row, 256 threads, D=512.
// ---------------------------------------------------------------------------
__global__ __launch_bounds__(256) void add_ln(
    const float* __restrict__ xa, const float* __restrict__ xb,
    const float* __restrict__ gs, const float* __restrict__ gb,
    float* __restrict__ dst, int scatter, int shift)
{
    const int row = blockIdx.x;
    const int tid = threadIdx.x;
    const float* pa = xa + (size_t)row * Dd;
    const float* pb = xb + (size_t)row * Dd;
    const float v0 = pa[tid] + pb[tid];
    const float v1 = pa[tid + 256] + pb[tid + 256];
    __shared__ float red1[8];
    __shared__ float red2[8];
    float s = v0 + v1;
    #pragma unroll
    for (int o = 16; o > 0; o >>= 1) s += __shfl_xor_sync(0xffffffffu, s, o);
    if ((tid & 31) == 0) red1[tid >> 5] = s;
    __syncthreads();
    const float mu = (red1[0] + red1[1] + red1[2] + red1[3] +
                      red1[4] + red1[5] + red1[6] + red1[7]) * (1.0f / Dd);
    const float d0 = v0 - mu, d1 = v1 - mu;
    float ss = d0 * d0 + d1 * d1;
    #pragma unroll
    for (int o = 16; o > 0; o >>= 1) ss += __shfl_xor_sync(0xffffffffu, ss, o);
    if ((tid & 31) == 0) red2[tid >> 5] = ss;
    __syncthreads();
    const float var = (red2[0] + red2[1] + red2[2] + red2[3] +
                       red2[4] + red2[5] + red2[6] + red2[7]) * (1.0f / Dd);
    const float rstd = rsqrtf(var + 1e-5f);
    size_t drow = row;
    if (scatter) {
        const int w = row / Ss, sidx = row % Ss;
        const int b = w / NWw, nw = w % NWw;
        const int tl = sidx / FQn, fq = sidx % FQn;
        int t = nw * WSZw + tl - shift;
        if (t < 0) t += Tt;
        drow = (size_t)(b * Tt + t) * FQn + fq;
    }
    float* pd = dst + drow * Dd;
    pd[tid]       = d0 * rstd * gs[tid]       + gb[tid];
    pd[tid + 256] = d1 * rstd * gs[tid + 256] + gb[tid + 256];
}

// ---------------------------------------------------------------------------
extern "C" void kernel_launch(void* const* d_in, const int* in_sizes, int n_in,
                              void* d_out, int out_size)
{
    const float* fqin = (const float*)d_in[0];
    const float* Wp   = (const float*)d_in[1];
    const float* bp   = (const float*)d_in[2];
    const float* Wqkv = (const float*)d_in[3];
    const float* bqkv = (const float*)d_in[4];
    const float* Wo   = (const float*)d_in[5];
    const float* bo   = (const float*)d_in[6];
    const float* ln1s = (const float*)d_in[7];
    const float* ln1b = (const float*)d_in[8];
    const float* W1   = (const float*)d_in[9];
    const float* b1   = (const float*)d_in[10];
    const float* W2   = (const float*)d_in[11];
    const float* b2   = (const float*)d_in[12];
    const float* ln2s = (const float*)d_in[13];
    const float* ln2b = (const float*)d_in[14];
    float* out = (float*)d_out;

    float *x, *xw, *tmp, *attn, *qkv, *ffn, *scores;
    cudaGetSymbolAddress((void**)&x,      g_x);
    cudaGetSymbolAddress((void**)&xw,     g_xw);
    cudaGetSymbolAddress((void**)&tmp,    g_tmp);
    cudaGetSymbolAddress((void**)&attn,   g_attn);
    cudaGetSymbolAddress((void**)&qkv,    g_qkv);
    cudaGetSymbolAddress((void**)&ffn,    g_ffn);
    cudaGetSymbolAddress((void**)&scores, g_scores);

    // Input projection: x = fq @ Wp^T + bp
    gemm_nt<<<dim3(Dd / 64, NTOK / 64), 256>>>(fqin, Dd, Wp, Dd, bp, x, Dd, Dd, 0);

    for (int i = 0; i < Ll; i++) {
        const int shifted = i & 1;
        const int shift = shifted ? HALFh : 0;

        // window gather (with roll for shifted layers)
        gather_win<<<NTOK * 128 / 256, 256>>>(x, xw, shift);

        // QKV projection
        gemm_nt<<<dim3(3 * Dd / 64, NTOK / 64), 256>>>(
            xw, Dd, Wqkv + (size_t)i * 3 * Dd * Dd, Dd,
            bqkv + (size_t)i * 3 * Dd, qkv, 3 * Dd, Dd, 0);

        // attention
        attn_scores<<<dim3(13, 13, WHn), 256>>>(qkv, scores, shifted);
        softmax_rows<<<WHn * Ss, 256>>>(scores);
        attn_av<<<dim3(13, 1, WHn), 256>>>(scores, qkv, attn);

        // output projection
        gemm_nt<<<dim3(Dd / 64, NTOK / 64), 256>>>(
            attn, Dd, Wo + (size_t)i * Dd * Dd, Dd,
            bo + (size_t)i * Dd, tmp, Dd, Dd, 0);

        // residual + LN1, scatter back (inverse roll)
        add_ln<<<NTOK, 256>>>(xw, tmp, ln1s + (size_t)i * Dd, ln1b + (size_t)i * Dd,
                              x, 1, shift);

        // FFN
        gemm_nt<<<dim3(DFFd / 64, NTOK / 64), 256>>>(
            x, Dd, W1 + (size_t)i * DFFd * Dd, Dd,
            b1 + (size_t)i * DFFd, ffn, DFFd, Dd, 1);
        gemm_nt<<<dim3(Dd / 64, NTOK / 64), 256>>>(
            ffn, DFFd, W2 + (size_t)i * Dd * DFFd, DFFd,
            b2 + (size_t)i * Dd, tmp, Dd, DFFd, 0);

        // residual + LN2 (final layer writes straight to d_out)
        add_ln<<<NTOK, 256>>>(x, tmp, ln2s + (size_t)i * Dd, ln2b + (size_t)i * Dd,
                              (i == Ll - 1) ? out : x, 0, 0);
    }
    (void)in_sizes; (void)n_in; (void)out_size;
}

// round 3
// speedup vs baseline: 2.2968x; 2.2968x over previous
#include <cuda_runtime.h>
#include <cstdint>

// Problem constants
#define Bb    2
#define Tt    48
#define FQn   100
#define Dd    512
#define Hh    8
#define HDd   64
#define DFFd  2048
#define Ll    6
#define WSZw  8
#define NWw   6          // windows per batch item (T/WSZ)
#define NWIN  12         // B * NWw
#define Ss    800        // WSZ * FQ
#define HALFh 4          // ceil(WSZ/2)
#define NTOK  9600       // B*T*FQ
#define WHn   96         // NWIN * H
#define QKVLD 1536       // 3*D row stride in qkv buffer

#define KST 20           // SMEM k-stride (16 + 4 pad; ≡4 mod 32 -> conflict-free)
#define VST 72           // SMEM n-stride for k-major V tile (≡8 mod 32)

// Scratch (device globals: allocation-guard safe)
__device__ float g_x[NTOK * Dd];
__device__ float g_xw[NTOK * Dd];
__device__ float g_tmp[NTOK * Dd];
__device__ float g_attn[NTOK * Dd];
__device__ float g_qkv[NTOK * 3 * Dd];
__device__ float g_ffn[NTOK * DFFd];
__device__ float g_scores[(size_t)WHn * Ss * Ss];

// ---------------------------------------------------------------------------
// tf32 helpers
// ---------------------------------------------------------------------------
__device__ __forceinline__ unsigned f2tf(float f) {
    unsigned u;
    asm("cvt.rna.tf32.f32 %0, %1;" : "=r"(u) : "f"(f));
    return u;
}

__device__ __forceinline__ void mma_tf32(
    float c[4], unsigned a0, unsigned a1, unsigned a2, unsigned a3,
    unsigned b0, unsigned b1)
{
    asm volatile(
        "mma.sync.aligned.m16n8k8.row.col.f32.tf32.tf32.f32 "
        "{%0,%1,%2,%3}, {%4,%5,%6,%7}, {%8,%9}, {%0,%1,%2,%3};"
        : "+f"(c[0]), "+f"(c[1]), "+f"(c[2]), "+f"(c[3])
        : "r"(a0), "r"(a1), "r"(a2), "r"(a3), "r"(b0), "r"(b1));
}

__device__ __forceinline__ uint4 tf4(float4 v) {
    return make_uint4(f2tf(v.x), f2tf(v.y), f2tf(v.z), f2tf(v.w));
}

// ---------------------------------------------------------------------------
// Tensor-core NT GEMM: C[N,M] = A[N,K] @ W[M,K]^T + bias[M]  (row-major)
// Block: 256 thr = 8 warps (4x2), tile 128x64, K-tile 16.
// Requires: rows(A) % 128 == 0, M % 64 == 0, K % 16 == 0.
// grid = (M/64, rows/128)
// ---------------------------------------------------------------------------
__global__ __launch_bounds__(256) void gemm_tc(
    const float* __restrict__ A, int lda,
    const float* __restrict__ W, int ldw,
    const float* __restrict__ bias,
    float* __restrict__ C, int ldc,
    int K, int relu)
{
    __shared__ unsigned As[128 * KST];
    __shared__ unsigned Bs[64 * KST];
    const int tid = threadIdx.x, lane = tid & 31, wid = tid >> 5;
    const int wm = (wid & 3) << 5, wn = (wid >> 2) << 5;
    const int bm = blockIdx.y << 7, bn = blockIdx.x << 6;
    const int am = tid >> 2, c4 = (tid & 3) << 2;
    float acc[2][4][4] = {};
    const float* pA0 = A + (size_t)(bm + am) * lda + c4;
    const float* pA1 = A + (size_t)(bm + am + 64) * lda + c4;
    const float* pB  = W + (size_t)(bn + am) * ldw + c4;
    float4 ra0 = *(const float4*)pA0;
    float4 ra1 = *(const float4*)pA1;
    float4 rb  = *(const float4*)pB;
    const int T = K >> 4;
    for (int t = 0; t < T; t++) {
        if (t) __syncthreads();
        *(uint4*)&As[am * KST + c4]        = tf4(ra0);
        *(uint4*)&As[(am + 64) * KST + c4] = tf4(ra1);
        *(uint4*)&Bs[am * KST + c4]        = tf4(rb);
        __syncthreads();
        if (t + 1 < T) {
            pA0 += 16; pA1 += 16; pB += 16;
            ra0 = *(const float4*)pA0;
            ra1 = *(const float4*)pA1;
            rb  = *(const float4*)pB;
        }
        #pragma unroll
        for (int kk = 0; kk < 16; kk += 8) {
            unsigned af[2][4], bf[4][2];
            const int c = kk + (lane & 3), r8 = lane >> 2;
            #pragma unroll
            for (int mt = 0; mt < 2; mt++) {
                const int r = wm + mt * 16 + r8;
                af[mt][0] = As[r * KST + c];
                af[mt][1] = As[(r + 8) * KST + c];
                af[mt][2] = As[r * KST + c + 4];
                af[mt][3] = As[(r + 8) * KST + c + 4];
            }
            #pragma unroll
            for (int nt = 0; nt < 4; nt++) {
                const int n = wn + nt * 8 + r8;
                bf[nt][0] = Bs[n * KST + c];
                bf[nt][1] = Bs[n * KST + c + 4];
            }
            #pragma unroll
            for (int mt = 0; mt < 2; mt++)
                #pragma unroll
                for (int nt = 0; nt < 4; nt++)
                    mma_tf32(acc[mt][nt], af[mt][0], af[mt][1], af[mt][2], af[mt][3],
                             bf[nt][0], bf[nt][1]);
        }
    }
    #pragma unroll
    for (int mt = 0; mt < 2; mt++) {
        const int row = bm + wm + mt * 16 + (lane >> 2);
        #pragma unroll
        for (int nt = 0; nt < 4; nt++) {
            const int col = bn + wn + nt * 8 + ((lane & 3) << 1);
            const float bx = bias[col], by = bias[col + 1];
            float v0 = acc[mt][nt][0] + bx, v1 = acc[mt][nt][1] + by;
            float v2 = acc[mt][nt][2] + bx, v3 = acc[mt][nt][3] + by;
            if (relu) {
                v0 = fmaxf(v0, 0.f); v1 = fmaxf(v1, 0.f);
                v2 = fmaxf(v2, 0.f); v3 = fmaxf(v3, 0.f);
            }
            float2 w0 = {v0, v1}, w1 = {v2, v3};
            *(float2*)&C[(size_t)row * ldc + col]       = w0;
            *(float2*)&C[(size_t)(row + 8) * ldc + col] = w1;
        }
    }
}

// ---------------------------------------------------------------------------
// Scores: S[wh,q,k] = (Q[q,:].K[k,:]) * 0.125 (+ shift mask), tensor-core.
// Block tile 128(q) x 64(k), K inner = 64 (4 tiles). grid = (13, 7, 96).
// ---------------------------------------------------------------------------
__global__ __launch_bounds__(256) void attn_scores_tc(
    const float* __restrict__ qkv, float* __restrict__ scores, int shifted)
{
    __shared__ unsigned As[128 * KST];
    __shared__ unsigned Bs[64 * KST];
    const int wh = blockIdx.z, w = wh >> 3, h = wh & 7;
    const int bm = blockIdx.y << 7, bn = blockIdx.x << 6;
    const int tid = threadIdx.x, lane = tid & 31, wid = tid >> 5;
    const int wm = (wid & 3) << 5, wn = (wid >> 2) << 5;
    const int am = tid >> 2, c4 = (tid & 3) << 2;
    float acc[2][4][4] = {};
    const float* base = qkv + (size_t)w * Ss * QKVLD + h * HDd;
    const int q0 = bm + am, q1 = bm + am + 64, kr = bn + am;
    const float* pA0 = base + (size_t)q0 * QKVLD + c4;
    const float* pA1 = base + (size_t)q1 * QKVLD + c4;
    const float* pB  = base + Dd + (size_t)kr * QKVLD + c4;
    const float4 z4 = {0.f, 0.f, 0.f, 0.f};
    float4 ra0 = (q0 < Ss) ? *(const float4*)pA0 : z4;
    float4 ra1 = (q1 < Ss) ? *(const float4*)pA1 : z4;
    float4 rb  = (kr < Ss) ? *(const float4*)pB  : z4;
    for (int t = 0; t < 4; t++) {
        if (t) __syncthreads();
        *(uint4*)&As[am * KST + c4]        = tf4(ra0);
        *(uint4*)&As[(am + 64) * KST + c4] = tf4(ra1);
        *(uint4*)&Bs[am * KST + c4]        = tf4(rb);
        __syncthreads();
        if (t + 1 < 4) {
            pA0 += 16; pA1 += 16; pB += 16;
            ra0 = (q0 < Ss) ? *(const float4*)pA0 : z4;
            ra1 = (q1 < Ss) ? *(const float4*)pA1 : z4;
            rb  = (kr < Ss) ? *(const float4*)pB  : z4;
        }
        #pragma unroll
        for (int kk = 0; kk < 16; kk += 8) {
            unsigned af[2][4], bf[4][2];
            const int c = kk + (lane & 3), r8 = lane >> 2;
            #pragma unroll
            for (int mt = 0; mt < 2; mt++) {
                const int r = wm + mt * 16 + r8;
                af[mt][0] = As[r * KST + c];
                af[mt][1] = As[(r + 8) * KST + c];
                af[mt][2] = As[r * KST + c + 4];
                af[mt][3] = As[(r + 8) * KST + c + 4];
            }
            #pragma unroll
            for (int nt = 0; nt < 4; nt++) {
                const int n = wn + nt * 8 + r8;
                bf[nt][0] = Bs[n * KST + c];
                bf[nt][1] = Bs[n * KST + c + 4];
            }
            #pragma unroll
            for (int mt = 0; mt < 2; mt++)
                #pragma unroll
                for (int nt = 0; nt < 4; nt++)
                    mma_tf32(acc[mt][nt], af[mt][0], af[mt][1], af[mt][2], af[mt][3],
                             bf[nt][0], bf[nt][1]);
        }
    }
    const bool maskw = (shifted != 0) && ((w % NWw) == 0);
    float* Cb = scores + (size_t)wh * Ss * Ss;
    #pragma unroll
    for (int mt = 0; mt < 2; mt++) {
        const int qa = bm + wm + mt * 16 + (lane >> 2);
        #pragma unroll
        for (int nt = 0; nt < 4; nt++) {
            const int kc = bn + wn + nt * 8 + ((lane & 3) << 1);
            #pragma unroll
            for (int e = 0; e < 4; e++) {
                const int q = qa + (e >> 1) * 8;
                const int k = kc + (e & 1);
                if (q >= Ss || k >= Ss) continue;
                float v = acc[mt][nt][e] * 0.125f;
                if (maskw) {
                    const int tq = q / FQn, tk = k / FQn;
                    if ((tq < HALFh) != (tk < HALFh)) v -= 1000.0f;
                }
                Cb[(size_t)q * Ss + k] = v;
            }
        }
    }
}

// ---------------------------------------------------------------------------
// O[wh,q,:] = P[wh,q,:] @ V[wh,:,:]  (P: 800x800 fp32, V: 800x64), tensor-core.
// Block tile 128(q) x 64(d), K = 800 (50 tiles). grid = (7, 96).
// V staged k-major: Vs[k][d] stride 72.
// ---------------------------------------------------------------------------
__global__ __launch_bounds__(256) void attn_av_tc(
    const float* __restrict__ scores, const float* __restrict__ qkv,
    float* __restrict__ attn)
{
    __shared__ unsigned As[128 * KST];
    __shared__ unsigned Vs[16 * VST];
    const int wh = blockIdx.y, w = wh >> 3, h = wh & 7;
    const int bm = blockIdx.x << 7;
    const int tid = threadIdx.x, lane = tid & 31, wid = tid >> 5;
    const int wm = (wid & 3) << 5, wn = (wid >> 2) << 5;
    const int am = tid >> 2, c4 = (tid & 3) << 2;
    const int vk = tid >> 4, vd4 = (tid & 15) << 2;
    float acc[2][4][4] = {};
    const float* Pb = scores + (size_t)wh * Ss * Ss;
    const float* Vb = qkv + (size_t)w * Ss * QKVLD + 2 * Dd + h * HDd;
    const int q0 = bm + am, q1 = bm + am + 64;
    const float* pA0 = Pb + (size_t)q0 * Ss + c4;
    const float* pA1 = Pb + (size_t)q1 * Ss + c4;
    const float* pV  = Vb + (size_t)vk * QKVLD + vd4;
    const float4 z4 = {0.f, 0.f, 0.f, 0.f};
    float4 ra0 = (q0 < Ss) ? *(const float4*)pA0 : z4;
    float4 ra1 = (q1 < Ss) ? *(const float4*)pA1 : z4;
    float4 rv  = *(const float4*)pV;
    for (int t = 0; t < 50; t++) {
        if (t) __syncthreads();
        *(uint4*)&As[am * KST + c4]        = tf4(ra0);
        *(uint4*)&As[(am + 64) * KST + c4] = tf4(ra1);
        *(uint4*)&Vs[vk * VST + vd4]       = tf4(rv);
        __syncthreads();
        if (t + 1 < 50) {
            pA0 += 16; pA1 += 16; pV += 16 * QKVLD;
            ra0 = (q0 < Ss) ? *(const float4*)pA0 : z4;
            ra1 = (q1 < Ss) ? *(const float4*)pA1 : z4;
            rv  = *(const float4*)pV;
        }
        #pragma unroll
        for (int kk = 0; kk < 16; kk += 8) {
            unsigned af[2][4], bf[4][2];
            const int c = kk + (lane & 3), r8 = lane >> 2;
            #pragma unroll
            for (int mt = 0; mt < 2; mt++) {
                const int r = wm + mt * 16 + r8;
                af[mt][0] = As[r * KST + c];
                af[mt][1] = As[(r + 8) * KST + c];
                af[mt][2] = As[r * KST + c + 4];
                af[mt][3] = As[(r + 8) * KST + c + 4];
            }
            #pragma unroll
            for (int nt = 0; nt < 4; nt++) {
                const int n = wn + nt * 8 + r8;
                bf[nt][0] = Vs[c * VST + n];
                bf[nt][1] = Vs[(c + 4) * VST + n];
            }
            #pragma unroll
            for (int mt = 0; mt < 2; mt++)
                #pragma unroll
                for (int nt = 0; nt < 4; nt++)
                    mma_tf32(acc[mt][nt], af[mt][0], af[mt][1], af[mt][2], af[mt][3],
                             bf[nt][0], bf[nt][1]);
        }
    }
    #pragma unroll
    for (int mt = 0; mt < 2; mt++) {
        const int q = bm + wm + mt * 16 + (lane >> 2);
        #pragma unroll
        for (int nt = 0; nt < 4; nt++) {
            const int col = wn + nt * 8 + ((lane & 3) << 1);
            if (q < Ss) {
                float2 w0 = {acc[mt][nt][0], acc[mt][nt][1]};
                *(float2*)&attn[(size_t)(w * Ss + q) * Dd + h * HDd + col] = w0;
            }
            if (q + 8 < Ss) {
                float2 w1 = {acc[mt][nt][2], acc[mt][nt][3]};
                *(float2*)&attn[(size_t)(w * Ss + q + 8) * Dd + h * HDd + col] = w1;
            }
        }
    }
}

// ---------------------------------------------------------------------------
// Window gather with roll: xw[w*S+s] = x[token(w,s,shift)]
// ---------------------------------------------------------------------------
__global__ __launch_bounds__(256) void gather_win(
    const float* __restrict__ x, float* __restrict__ xw, int shift)
{
    const int idx = blockIdx.x * 256 + threadIdx.x;
    const int row = idx >> 7;
    const int c = idx & 127;
    const int w = row / Ss, sidx = row % Ss;
    const int b = w / NWw, nw = w % NWw;
    const int tl = sidx / FQn, fq = sidx % FQn;
    int t = nw * WSZw + tl - shift;
    if (t < 0) t += Tt;
    const size_t n = (size_t)(b * Tt + t) * FQn + fq;
    ((float4*)xw)[(size_t)row * 128 + c] = ((const float4*)x)[n * 128 + c];
}

// ---------------------------------------------------------------------------
// Row softmax over 800 entries; one block per row.
// ---------------------------------------------------------------------------
__global__ __launch_bounds__(256) void softmax_rows(float* __restrict__ scores)
{
    float* p = scores + (size_t)blockIdx.x * Ss;
    const int tid = threadIdx.x;
    float v[4];
    float lmax = -3.0e38f;
    #pragma unroll
    for (int i = 0; i < 4; i++) {
        const int idx = tid + (i << 8);
        v[i] = (idx < Ss) ? p[idx] : -3.0e38f;
        lmax = fmaxf(lmax, v[i]);
    }
    __shared__ float redm[8];
    __shared__ float reds[8];
    #pragma unroll
    for (int o = 16; o > 0; o >>= 1)
        lmax = fmaxf(lmax, __shfl_xor_sync(0xffffffffu, lmax, o));
    if ((tid & 31) == 0) redm[tid >> 5] = lmax;
    __syncthreads();
    const float m = fmaxf(fmaxf(fmaxf(redm[0], redm[1]), fmaxf(redm[2], redm[3])),
                          fmaxf(fmaxf(redm[4], redm[5]), fmaxf(redm[6], redm[7])));
    float lsum = 0.f;
    #pragma unroll
    for (int i = 0; i < 4; i++) {
        const int idx = tid + (i << 8);
        if (idx < Ss) { v[i] = __expf(v[i] - m); lsum += v[i]; }
    }
    #pragma unroll
    for (int o = 16; o > 0; o >>= 1)
        lsum += __shfl_xor_sync(0xffffffffu, lsum, o);
    if ((tid & 31) == 0) reds[tid >> 5] = lsum;
    __syncthreads();
    const float ssum = reds[0] + reds[1] + reds[2] + reds[3] +
                       reds[4] + reds[5] + reds[6] + reds[7];
    const float inv = 1.0f / ssum;
    #pragma unroll
    for (int i = 0; i < 4; i++) {
        const int idx = tid + (i << 8);
        if (idx < Ss) p[idx] = v[i] * inv;
    }
}

// ---------------------------------------------------------------------------
// dst[row'] = LayerNorm(xa[row] + xb[row]) * gs + gb
// ---------------------------------------------------------------------------
__global__ __launch_bounds__(256) void add_ln(
    const float* __restrict__ xa, const float* __restrict__ xb,
    const float* __restrict__ gs, const float* __restrict__ gb,
    float* __restrict__ dst, int scatter, int shift)
{
    const int row = blockIdx.x;
    const int tid = threadIdx.x;
    const float* pa = xa + (size_t)row * Dd;
    const float* pb = xb + (size_t)row * Dd;
    const float v0 = pa[tid] + pb[tid];
    const float v1 = pa[tid + 256] + pb[tid + 256];
    __shared__ float red1[8];
    __shared__ float red2[8];
    float s = v0 + v1;
    #pragma unroll
    for (int o = 16; o > 0; o >>= 1) s += __shfl_xor_sync(0xffffffffu, s, o);
    if ((tid & 31) == 0) red1[tid >> 5] = s;
    __syncthreads();
    const float mu = (red1[0] + red1[1] + red1[2] + red1[3] +
                      red1[4] + red1[5] + red1[6] + red1[7]) * (1.0f / Dd);
    const float d0 = v0 - mu, d1 = v1 - mu;
    float ss = d0 * d0 + d1 * d1;
    #pragma unroll
    for (int o = 16; o > 0; o >>= 1) ss += __shfl_xor_sync(0xffffffffu, ss, o);
    if ((tid & 31) == 0) red2[tid >> 5] = ss;
    __syncthreads();
    const float var = (red2[0] + red2[1] + red2[2] + red2[3] +
                       red2[4] + red2[5] + red2[6] + red2[7]) * (1.0f / Dd);
    const float rstd = rsqrtf(var + 1e-5f);
    size_t drow = row;
    if (scatter) {
        const int w = row / Ss, sidx = row % Ss;
        const int b = w / NWw, nw = w % NWw;
        const int tl = sidx / FQn, fq = sidx % FQn;
        int t = nw * WSZw + tl - shift;
        if (t < 0) t += Tt;
        drow = (size_t)(b * Tt + t) * FQn + fq;
    }
    float* pd = dst + drow * Dd;
    pd[tid]       = d0 * rstd * gs[tid]       + gb[tid];
    pd[tid + 256] = d1 * rstd * gs[tid + 256] + gb[tid + 256];
}

// ---------------------------------------------------------------------------
extern "C" void kernel_launch(void* const* d_in, const int* in_sizes, int n_in,
                              void* d_out, int out_size)
{
    const float* fqin = (const float*)d_in[0];
    const float* Wp   = (const float*)d_in[1];
    const float* bp   = (const float*)d_in[2];
    const float* Wqkv = (const float*)d_in[3];
    const float* bqkv = (const float*)d_in[4];
    const float* Wo   = (const float*)d_in[5];
    const float* bo   = (const float*)d_in[6];
    const float* ln1s = (const float*)d_in[7];
    const float* ln1b = (const float*)d_in[8];
    const float* W1   = (const float*)d_in[9];
    const float* b1   = (const float*)d_in[10];
    const float* W2   = (const float*)d_in[11];
    const float* b2   = (const float*)d_in[12];
    const float* ln2s = (const float*)d_in[13];
    const float* ln2b = (const float*)d_in[14];
    float* out = (float*)d_out;

    float *x, *xw, *tmp, *attn, *qkv, *ffn, *scores;
    cudaGetSymbolAddress((void**)&x,      g_x);
    cudaGetSymbolAddress((void**)&xw,     g_xw);
    cudaGetSymbolAddress((void**)&tmp,    g_tmp);
    cudaGetSymbolAddress((void**)&attn,   g_attn);
    cudaGetSymbolAddress((void**)&qkv,    g_qkv);
    cudaGetSymbolAddress((void**)&ffn,    g_ffn);
    cudaGetSymbolAddress((void**)&scores, g_scores);

    // Input projection: x = fq @ Wp^T + bp
    gemm_tc<<<dim3(Dd / 64, NTOK / 128), 256>>>(fqin, Dd, Wp, Dd, bp, x, Dd, Dd, 0);

    for (int i = 0; i < Ll; i++) {
        const int shifted = i & 1;
        const int shift = shifted ? HALFh : 0;

        // window gather (with roll for shifted layers)
        gather_win<<<NTOK * 128 / 256, 256>>>(x, xw, shift);

        // QKV projection
        gemm_tc<<<dim3(3 * Dd / 64, NTOK / 128), 256>>>(
            xw, Dd, Wqkv + (size_t)i * 3 * Dd * Dd, Dd,
            bqkv + (size_t)i * 3 * Dd, qkv, 3 * Dd, Dd, 0);

        // attention
        attn_scores_tc<<<dim3(13, 7, WHn), 256>>>(qkv, scores, shifted);
        softmax_rows<<<WHn * Ss, 256>>>(scores);
        attn_av_tc<<<dim3(7, WHn), 256>>>(scores, qkv, attn);

        // output projection
        gemm_tc<<<dim3(Dd / 64, NTOK / 128), 256>>>(
            attn, Dd, Wo + (size_t)i * Dd * Dd, Dd,
            bo + (size_t)i * Dd, tmp, Dd, Dd, 0);

        // residual + LN1, scatter back (inverse roll)
        add_ln<<<NTOK, 256>>>(xw, tmp, ln1s + (size_t)i * Dd, ln1b + (size_t)i * Dd,
                              x, 1, shift);

        // FFN
        gemm_tc<<<dim3(DFFd / 64, NTOK / 128), 256>>>(
            x, Dd, W1 + (size_t)i * DFFd * Dd, Dd,
            b1 + (size_t)i * DFFd, ffn, DFFd, Dd, 1);
        gemm_tc<<<dim3(Dd / 64, NTOK / 128), 256>>>(
            ffn, DFFd, W2 + (size_t)i * Dd * DFFd, DFFd,
            b2 + (size_t)i * Dd, tmp, Dd, DFFd, 0);

        // residual + LN2 (final layer writes straight to d_out)
        add_ln<<<NTOK, 256>>>(x, tmp, ln2s + (size_t)i * Dd, ln2b + (size_t)i * Dd,
                              (i == Ll - 1) ? out : x, 0, 0);
    }
    (void)in_sizes; (void)n_in; (void)out_size;
}

// round 5
// speedup vs baseline: 2.7565x; 1.2002x over previous
#include <cuda_runtime.h>
#include <cstdint>

// Problem constants
#define Bb    2
#define Tt    48
#define FQn   100
#define Dd    512
#define Hh    8
#define HDd   64
#define DFFd  2048
#define Ll    6
#define WSZw  8
#define NWw   6          // windows per batch item (T/WSZ)
#define NWIN  12         // B * NWw
#define Ss    800        // WSZ * FQ
#define HALFh 4          // ceil(WSZ/2)
#define NTOK  9600       // B*T*FQ
#define WHn   96         // NWIN * H
#define QKVLD 1536       // 3*D row stride in qkv buffer

#define KST 20           // SMEM k-stride for gemm (16+4 pad; ≡4 mod 32)
#define QPST 68          // SMEM stride for 64-wide q/k/p tiles (≡4 mod 32)
#define VST 72           // SMEM stride for k-major V tile (≡8 mod 32)

// Flash SMEM layout (words)
#define FA_QS   0
#define FA_PS   (128 * QPST)
#define FA_KV   (FA_PS + 128 * QPST)
#define FA_REDM (FA_KV + 64 * VST)
#define FA_REDL (FA_REDM + 256)
#define FA_WORDS (FA_REDL + 256)
#define FA_BYTES (FA_WORDS * 4)

// Scratch (device globals: allocation-guard safe)
__device__ float g_x[NTOK * Dd];
__device__ float g_xw[NTOK * Dd];
__device__ float g_tmp[NTOK * Dd];
__device__ float g_attn[NTOK * Dd];
__device__ float g_qkv[NTOK * 3 * Dd];
__device__ float g_ffn[NTOK * DFFd];

// ---------------------------------------------------------------------------
// tf32 helpers
// ---------------------------------------------------------------------------
__device__ __forceinline__ unsigned f2tf(float f) {
    unsigned u;
    asm("cvt.rna.tf32.f32 %0, %1;" : "=r"(u) : "f"(f));
    return u;
}

__device__ __forceinline__ void mma_tf32(
    float c[4], unsigned a0, unsigned a1, unsigned a2, unsigned a3,
    unsigned b0, unsigned b1)
{
    asm volatile(
        "mma.sync.aligned.m16n8k8.row.col.f32.tf32.tf32.f32 "
        "{%0,%1,%2,%3}, {%4,%5,%6,%7}, {%8,%9}, {%0,%1,%2,%3};"
        : "+f"(c[0]), "+f"(c[1]), "+f"(c[2]), "+f"(c[3])
        : "r"(a0), "r"(a1), "r"(a2), "r"(a3), "r"(b0), "r"(b1));
}

__device__ __forceinline__ uint4 tf4(float4 v) {
    return make_uint4(f2tf(v.x), f2tf(v.y), f2tf(v.z), f2tf(v.w));
}

// ---------------------------------------------------------------------------
// Tensor-core NT GEMM: C[N,M] = A[N,K] @ W[M,K]^T + bias[M]  (row-major)
// Block: 256 thr = 8 warps (4x2), tile 128x64, K-tile 16.
// grid = (M/64, rows/128)
// ---------------------------------------------------------------------------
__global__ __launch_bounds__(256) void gemm_tc(
    const float* __restrict__ A, int lda,
    const float* __restrict__ W, int ldw,
    const float* __restrict__ bias,
    float* __restrict__ C, int ldc,
    int K, int relu)
{
    __shared__ unsigned As[128 * KST];
    __shared__ unsigned Bs[64 * KST];
    const int tid = threadIdx.x, lane = tid & 31, wid = tid >> 5;
    const int wm = (wid & 3) << 5, wn = (wid >> 2) << 5;
    const int bm = blockIdx.y << 7, bn = blockIdx.x << 6;
    const int am = tid >> 2, c4 = (tid & 3) << 2;
    float acc[2][4][4] = {};
    const float* pA0 = A + (size_t)(bm + am) * lda + c4;
    const float* pA1 = A + (size_t)(bm + am + 64) * lda + c4;
    const float* pB  = W + (size_t)(bn + am) * ldw + c4;
    float4 ra0 = *(const float4*)pA0;
    float4 ra1 = *(const float4*)pA1;
    float4 rb  = *(const float4*)pB;
    const int T = K >> 4;
    for (int t = 0; t < T; t++) {
        if (t) __syncthreads();
        *(uint4*)&As[am * KST + c4]        = tf4(ra0);
        *(uint4*)&As[(am + 64) * KST + c4] = tf4(ra1);
        *(uint4*)&Bs[am * KST + c4]        = tf4(rb);
        __syncthreads();
        if (t + 1 < T) {
            pA0 += 16; pA1 += 16; pB += 16;
            ra0 = *(const float4*)pA0;
            ra1 = *(const float4*)pA1;
            rb  = *(const float4*)pB;
        }
        #pragma unroll
        for (int kk = 0; kk < 16; kk += 8) {
            unsigned af[2][4], bf[4][2];
            const int c = kk + (lane & 3), r8 = lane >> 2;
            #pragma unroll
            for (int mt = 0; mt < 2; mt++) {
                const int r = wm + mt * 16 + r8;
                af[mt][0] = As[r * KST + c];
                af[mt][1] = As[(r + 8) * KST + c];
                af[mt][2] = As[r * KST + c + 4];
                af[mt][3] = As[(r + 8) * KST + c + 4];
            }
            #pragma unroll
            for (int nt = 0; nt < 4; nt++) {
                const int n = wn + nt * 8 + r8;
                bf[nt][0] = Bs[n * KST + c];
                bf[nt][1] = Bs[n * KST + c + 4];
            }
            #pragma unroll
            for (int mt = 0; mt < 2; mt++)
                #pragma unroll
                for (int nt = 0; nt < 4; nt++)
                    mma_tf32(acc[mt][nt], af[mt][0], af[mt][1], af[mt][2], af[mt][3],
                             bf[nt][0], bf[nt][1]);
        }
    }
    #pragma unroll
    for (int mt = 0; mt < 2; mt++) {
        const int row = bm + wm + mt * 16 + (lane >> 2);
        #pragma unroll
        for (int nt = 0; nt < 4; nt++) {
            const int col = bn + wn + nt * 8 + ((lane & 3) << 1);
            const float bx = bias[col], by = bias[col + 1];
            float v0 = acc[mt][nt][0] + bx, v1 = acc[mt][nt][1] + by;
            float v2 = acc[mt][nt][2] + bx, v3 = acc[mt][nt][3] + by;
            if (relu) {
                v0 = fmaxf(v0, 0.f); v1 = fmaxf(v1, 0.f);
                v2 = fmaxf(v2, 0.f); v3 = fmaxf(v3, 0.f);
            }
            float2 w0 = {v0, v1}, w1 = {v2, v3};
            *(float2*)&C[(size_t)row * ldc + col]       = w0;
            *(float2*)&C[(size_t)(row + 8) * ldc + col] = w1;
        }
    }
}

// ---------------------------------------------------------------------------
// Fused flash attention: per (128-q tile, window-head), online softmax.
// grid = (7, 96), block 256 (8 warps 4m x 2n). Dynamic SMEM = FA_BYTES.
// ---------------------------------------------------------------------------
__global__ __launch_bounds__(256) void flash_attn(
    const float* __restrict__ qkv, float* __restrict__ attn, int shifted)
{
    extern __shared__ unsigned sm[];
    unsigned* Qs = sm + FA_QS;
    unsigned* Ps = sm + FA_PS;
    unsigned* KV = sm + FA_KV;
    float* redM = (float*)(sm + FA_REDM);
    float* redL = (float*)(sm + FA_REDL);

    const int wh = blockIdx.y, w = wh >> 3, h = wh & 7;
    const int bm = blockIdx.x << 7;
    const int tid = threadIdx.x, lane = tid & 31, wid = tid >> 5;
    const int wm = (wid & 3) << 5, wn = (wid >> 2) << 5;
    const int wnIdx = wid >> 2;
    const int r8 = lane >> 2, l3 = lane & 3;
    const float* base = qkv + (size_t)w * Ss * QKVLD + h * HDd;
    const float4 z4 = {0.f, 0.f, 0.f, 0.f};
    const bool maskw = (shifted != 0) && ((w % NWw) == 0);

    // Load Q tile [128 x 64] into Qs (tf32, stride QPST)
    {
        const int cc = (tid & 3) << 2;
        #pragma unroll
        for (int i = 0; i < 2; i++) {
            const int r = (tid >> 2) + (i << 6);
            const int q = bm + r;
            const float* p = base + (size_t)q * QKVLD + cc;
            #pragma unroll
            for (int j = 0; j < 4; j++) {
                float4 v = (q < Ss) ? *(const float4*)(p + 16 * j) : z4;
                *(uint4*)&Qs[r * QPST + cc + 16 * j] = tf4(v);
            }
        }
    }

    float accO[2][4][4] = {};
    float mst[2][2] = {{-1e30f, -1e30f}, {-1e30f, -1e30f}};
    float lst[2][2] = {{0.f, 0.f}, {0.f, 0.f}};

    for (int kt = 0; kt < 13; kt++) {
        const int k0 = kt << 6;
        __syncthreads();   // protect KV + Ps from previous iteration's MMA reads
        // Load K tile [64 x 64] -> KV (stride QPST)
        {
            const int kr = tid >> 2, cc = (tid & 3) << 2;
            const int gk = k0 + kr;
            const float* p = base + Dd + (size_t)gk * QKVLD + cc;
            #pragma unroll
            for (int j = 0; j < 4; j++) {
                float4 v = (gk < Ss) ? *(const float4*)(p + 16 * j) : z4;
                *(uint4*)&KV[kr * QPST + cc + 16 * j] = tf4(v);
            }
        }
        __syncthreads();

        // S = Q @ K^T
        float s[2][4][4] = {};
        #pragma unroll
        for (int kk = 0; kk < 64; kk += 8) {
            unsigned af[2][4], bf[4][2];
            const int c = kk + l3;
            #pragma unroll
            for (int mt = 0; mt < 2; mt++) {
                const int r = wm + mt * 16 + r8;
                af[mt][0] = Qs[r * QPST + c];
                af[mt][1] = Qs[(r + 8) * QPST + c];
                af[mt][2] = Qs[r * QPST + c + 4];
                af[mt][3] = Qs[(r + 8) * QPST + c + 4];
            }
            #pragma unroll
            for (int nt = 0; nt < 4; nt++) {
                const int n = wn + nt * 8 + r8;
                bf[nt][0] = KV[n * QPST + c];
                bf[nt][1] = KV[n * QPST + c + 4];
            }
            #pragma unroll
            for (int mt = 0; mt < 2; mt++)
                #pragma unroll
                for (int nt = 0; nt < 4; nt++)
                    mma_tf32(s[mt][nt], af[mt][0], af[mt][1], af[mt][2], af[mt][3],
                             bf[nt][0], bf[nt][1]);
        }

        // scale + mask + OOB; local row max
        float lm[2][2] = {{-1e30f, -1e30f}, {-1e30f, -1e30f}};
        #pragma unroll
        for (int mt = 0; mt < 2; mt++) {
            #pragma unroll
            for (int e = 0; e < 4; e++) {
                const int eh = e >> 1;
                const int q = bm + wm + mt * 16 + r8 + eh * 8;
                const int tq = q / FQn;
                #pragma unroll
                for (int nt = 0; nt < 4; nt++) {
                    const int k = k0 + wn + nt * 8 + (l3 << 1) + (e & 1);
                    float v = s[mt][nt][e] * 0.125f;
                    if (maskw) {
                        const int tk = k / FQn;
                        if ((tq < HALFh) != (tk < HALFh)) v -= 1000.0f;
                    }
                    if (k >= Ss) v = -1e30f;
                    s[mt][nt][e] = v;
                    lm[mt][eh] = fmaxf(lm[mt][eh], v);
                }
            }
        }
        // reduce max across lane&3 quad, publish per-warp-col
        #pragma unroll
        for (int mt = 0; mt < 2; mt++)
            #pragma unroll
            for (int eh = 0; eh < 2; eh++) {
                float v = lm[mt][eh];
                v = fmaxf(v, __shfl_xor_sync(0xffffffffu, v, 1));
                v = fmaxf(v, __shfl_xor_sync(0xffffffffu, v, 2));
                lm[mt][eh] = v;
                redM[wnIdx * 128 + wm + mt * 16 + eh * 8 + r8] = v;
            }
        __syncthreads();

        // m_new, alpha, p, local sums; store P; load V; rescale O
        float ls[2][2];
        float mnew[2][2];
        #pragma unroll
        for (int mt = 0; mt < 2; mt++) {
            #pragma unroll
            for (int eh = 0; eh < 2; eh++) {
                const int r = wm + mt * 16 + eh * 8 + r8;
                const float comb = fmaxf(redM[r], redM[128 + r]);
                const float mn = fmaxf(mst[mt][eh], comb);
                mnew[mt][eh] = mn;
                const float alpha = __expf(mst[mt][eh] - mn);
                mst[mt][eh] = mn;
                #pragma unroll
                for (int nt = 0; nt < 4; nt++) {
                    accO[mt][nt][eh * 2]     *= alpha;
                    accO[mt][nt][eh * 2 + 1] *= alpha;
                }
                lst[mt][eh] *= alpha;
                ls[mt][eh] = 0.f;
            }
        }
        #pragma unroll
        for (int mt = 0; mt < 2; mt++) {
            #pragma unroll
            for (int eh = 0; eh < 2; eh++) {
                const int r = wm + mt * 16 + eh * 8 + r8;
                #pragma unroll
                for (int nt = 0; nt < 4; nt++) {
                    const float p0 = __expf(s[mt][nt][eh * 2]     - mnew[mt][eh]);
                    const float p1 = __expf(s[mt][nt][eh * 2 + 1] - mnew[mt][eh]);
                    ls[mt][eh] += p0 + p1;
                    uint2 pp = {f2tf(p0), f2tf(p1)};
                    *(uint2*)&Ps[r * QPST + wn + nt * 8 + (l3 << 1)] = pp;
                }
                float v = ls[mt][eh];
                v += __shfl_xor_sync(0xffffffffu, v, 1);
                v += __shfl_xor_sync(0xffffffffu, v, 2);
                redL[wnIdx * 128 + r] = v;
            }
        }
        // Load V tile [64 x 64] -> KV k-major (stride VST); S-MMA reads done
        {
            const int vk = tid >> 2, cc = (tid & 3) << 2;
            const int gk = k0 + vk;
            const float* p = base + 2 * Dd + (size_t)gk * QKVLD + cc;
            #pragma unroll
            for (int j = 0; j < 4; j++) {
                float4 v = (gk < Ss) ? *(const float4*)(p + 16 * j) : z4;
                *(uint4*)&KV[vk * VST + cc + 16 * j] = tf4(v);
            }
        }
        __syncthreads();   // Ps, redL, V ready

        #pragma unroll
        for (int mt = 0; mt < 2; mt++)
            #pragma unroll
            for (int eh = 0; eh < 2; eh++) {
                const int r = wm + mt * 16 + eh * 8 + r8;
                lst[mt][eh] += redL[r] + redL[128 + r];
            }

        // O += P @ V
        #pragma unroll
        for (int kk = 0; kk < 64; kk += 8) {
            unsigned af[2][4], bf[4][2];
            const int c = kk + l3;
            #pragma unroll
            for (int mt = 0; mt < 2; mt++) {
                const int r = wm + mt * 16 + r8;
                af[mt][0] = Ps[r * QPST + c];
                af[mt][1] = Ps[(r + 8) * QPST + c];
                af[mt][2] = Ps[r * QPST + c + 4];
                af[mt][3] = Ps[(r + 8) * QPST + c + 4];
            }
            #pragma unroll
            for (int nt = 0; nt < 4; nt++) {
                const int n = wn + nt * 8 + r8;
                bf[nt][0] = KV[c * VST + n];
                bf[nt][1] = KV[(c + 4) * VST + n];
            }
            #pragma unroll
            for (int mt = 0; mt < 2; mt++)
                #pragma unroll
                for (int nt = 0; nt < 4; nt++)
                    mma_tf32(accO[mt][nt], af[mt][0], af[mt][1], af[mt][2], af[mt][3],
                             bf[nt][0], bf[nt][1]);
        }
    }

    // Epilogue: O /= l, store to attn
    #pragma unroll
    for (int mt = 0; mt < 2; mt++) {
        #pragma unroll
        for (int eh = 0; eh < 2; eh++) {
            const int q = bm + wm + mt * 16 + eh * 8 + r8;
            if (q >= Ss) continue;
            const float inv = 1.0f / lst[mt][eh];
            #pragma unroll
            for (int nt = 0; nt < 4; nt++) {
                const int col = wn + nt * 8 + (l3 << 1);
                float2 o2 = {accO[mt][nt][eh * 2] * inv, accO[mt][nt][eh * 2 + 1] * inv};
                *(float2*)&attn[(size_t)(w * Ss + q) * Dd + h * HDd + col] = o2;
            }
        }
    }
}

// ---------------------------------------------------------------------------
// Window gather with roll: xw[w*S+s] = x[token(w,s,shift)]
// ---------------------------------------------------------------------------
__global__ __launch_bounds__(256) void gather_win(
    const float* __restrict__ x, float* __restrict__ xw, int shift)
{
    const int idx = blockIdx.x * 256 + threadIdx.x;
    const int row = idx >> 7;
    const int c = idx & 127;
    const int w = row / Ss, sidx = row % Ss;
    const int b = w / NWw, nw = w % NWw;
    const int tl = sidx / FQn, fq = sidx % FQn;
    int t = nw * WSZw + tl - shift;
    if (t < 0) t += Tt;
    const size_t n = (size_t)(b * Tt + t) * FQn + fq;
    ((float4*)xw)[(size_t)row * 128 + c] = ((const float4*)x)[n * 128 + c];
}

// ---------------------------------------------------------------------------
// dst[row'] = LayerNorm(xa[row] + xb[row]) * gs + gb
// ---------------------------------------------------------------------------
__global__ __launch_bounds__(256) void add_ln(
    const float* __restrict__ xa, const float* __restrict__ xb,
    const float* __restrict__ gs, const float* __restrict__ gb,
    float* __restrict__ dst, int scatter, int shift)
{
    const int row = blockIdx.x;
    const int tid = threadIdx.x;
    const float* pa = xa + (size_t)row * Dd;
    const float* pb = xb + (size_t)row * Dd;
    const float v0 = pa[tid] + pb[tid];
    const float v1 = pa[tid + 256] + pb[tid + 256];
    __shared__ float red1[8];
    __shared__ float red2[8];
    float s = v0 + v1;
    #pragma unroll
    for (int o = 16; o > 0; o >>= 1) s += __shfl_xor_sync(0xffffffffu, s, o);
    if ((tid & 31) == 0) red1[tid >> 5] = s;
    __syncthreads();
    const float mu = (red1[0] + red1[1] + red1[2] + red1[3] +
                      red1[4] + red1[5] + red1[6] + red1[7]) * (1.0f / Dd);
    const float d0 = v0 - mu, d1 = v1 - mu;
    float ss = d0 * d0 + d1 * d1;
    #pragma unroll
    for (int o = 16; o > 0; o >>= 1) ss += __shfl_xor_sync(0xffffffffu, ss, o);
    if ((tid & 31) == 0) red2[tid >> 5] = ss;
    __syncthreads();
    const float var = (red2[0] + red2[1] + red2[2] + red2[3] +
                       red2[4] + red2[5] + red2[6] + red2[7]) * (1.0f / Dd);
    const float rstd = rsqrtf(var + 1e-5f);
    size_t drow = row;
    if (scatter) {
        const int w = row / Ss, sidx = row % Ss;
        const int b = w / NWw, nw = w % NWw;
        const int tl = sidx / FQn, fq = sidx % FQn;
        int t = nw * WSZw + tl - shift;
        if (t < 0) t += Tt;
        drow = (size_t)(b * Tt + t) * FQn + fq;
    }
    float* pd = dst + drow * Dd;
    pd[tid]       = d0 * rstd * gs[tid]       + gb[tid];
    pd[tid + 256] = d1 * rstd * gs[tid + 256] + gb[tid + 256];
}

// ---------------------------------------------------------------------------
extern "C" void kernel_launch(void* const* d_in, const int* in_sizes, int n_in,
                              void* d_out, int out_size)
{
    const float* fqin = (const float*)d_in[0];
    const float* Wp   = (const float*)d_in[1];
    const float* bp   = (const float*)d_in[2];
    const float* Wqkv = (const float*)d_in[3];
    const float* bqkv = (const float*)d_in[4];
    const float* Wo   = (const float*)d_in[5];
    const float* bo   = (const float*)d_in[6];
    const float* ln1s = (const float*)d_in[7];
    const float* ln1b = (const float*)d_in[8];
    const float* W1   = (const float*)d_in[9];
    const float* b1   = (const float*)d_in[10];
    const float* W2   = (const float*)d_in[11];
    const float* b2   = (const float*)d_in[12];
    const float* ln2s = (const float*)d_in[13];
    const float* ln2b = (const float*)d_in[14];
    float* out = (float*)d_out;

    float *x, *xw, *tmp, *attn, *qkv, *ffn;
    cudaGetSymbolAddress((void**)&x,    g_x);
    cudaGetSymbolAddress((void**)&xw,   g_xw);
    cudaGetSymbolAddress((void**)&tmp,  g_tmp);
    cudaGetSymbolAddress((void**)&attn, g_attn);
    cudaGetSymbolAddress((void**)&qkv,  g_qkv);
    cudaGetSymbolAddress((void**)&ffn,  g_ffn);

    cudaFuncSetAttribute(flash_attn,
                         cudaFuncAttributeMaxDynamicSharedMemorySize, FA_BYTES);

    // Input projection: x = fq @ Wp^T + bp
    gemm_tc<<<dim3(Dd / 64, NTOK / 128), 256>>>(fqin, Dd, Wp, Dd, bp, x, Dd, Dd, 0);

    for (int i = 0; i < Ll; i++) {
        const int shifted = i & 1;
        const int shift = shifted ? HALFh : 0;

        // window gather (with roll for shifted layers)
        gather_win<<<NTOK * 128 / 256, 256>>>(x, xw, shift);

        // QKV projection
        gemm_tc<<<dim3(3 * Dd / 64, NTOK / 128), 256>>>(
            xw, Dd, Wqkv + (size_t)i * 3 * Dd * Dd, Dd,
            bqkv + (size_t)i * 3 * Dd, qkv, 3 * Dd, Dd, 0);

        // fused attention (scores + mask + softmax + AV)
        flash_attn<<<dim3(7, WHn), 256, FA_BYTES>>>(qkv, attn, shifted);

        // output projection
        gemm_tc<<<dim3(Dd / 64, NTOK / 128), 256>>>(
            attn, Dd, Wo + (size_t)i * Dd * Dd, Dd,
            bo + (size_t)i * Dd, tmp, Dd, Dd, 0);

        // residual + LN1, scatter back (inverse roll)
        add_ln<<<NTOK, 256>>>(xw, tmp, ln1s + (size_t)i * Dd, ln1b + (size_t)i * Dd,
                              x, 1, shift);

        // FFN
        gemm_tc<<<dim3(DFFd / 64, NTOK / 128), 256>>>(
            x, Dd, W1 + (size_t)i * DFFd * Dd, Dd,
            b1 + (size_t)i * DFFd, ffn, DFFd, Dd, 1);
        gemm_tc<<<dim3(Dd / 64, NTOK / 128), 256>>>(
            ffn, DFFd, W2 + (size_t)i * Dd * DFFd, DFFd,
            b2 + (size_t)i * Dd, tmp, Dd, DFFd, 0);

        // residual + LN2 (final layer writes straight to d_out)
        add_ln<<<NTOK, 256>>>(x, tmp, ln2s + (size_t)i * Dd, ln2b + (size_t)i * Dd,
                              (i == Ll - 1) ? out : x, 0, 0);
    }
    (void)in_sizes; (void)n_in; (void)out_size;
}

// round 8
// speedup vs baseline: 3.0587x; 1.1096x over previous
#include <cuda_runtime.h>
#include <cstdint>

// Problem constants
#define Bb    2
#define Tt    48
#define FQn   100
#define Dd    512
#define Hh    8
#define HDd   64
#define DFFd  2048
#define Ll    6
#define WSZw  8
#define NWw   6          // windows per batch item (T/WSZ)
#define NWIN  12         // B * NWw
#define Ss    800        // WSZ * FQ
#define HALFh 4          // ceil(WSZ/2)
#define NTOK  9600       // B*T*FQ
#define WHn   96         // NWIN * H
#define QKVLD 1536       // 3*D row stride in qkv buffer

#define BKST 20          // gemm SMEM k-stride (16+4 pad; ≡4 mod 32)
#define QPST 68          // SMEM stride for 64-wide q/k/p tiles (≡4 mod 32)
#define VST 72           // SMEM stride for k-major V tile (≡8 mod 32)

// Flash SMEM layout (words)
#define FA_QS   0
#define FA_PS   (128 * QPST)
#define FA_KV   (FA_PS + 128 * QPST)
#define FA_REDM (FA_KV + 64 * VST)
#define FA_REDL (FA_REDM + 256)
#define FA_WORDS (FA_REDL + 256)
#define FA_BYTES (FA_WORDS * 4)

// Scratch (device globals: allocation-guard safe)
__device__ float g_x[NTOK * Dd];
__device__ float g_xw[NTOK * Dd];
__device__ float g_tmp[NTOK * Dd];
__device__ float g_attn[NTOK * Dd];
__device__ float g_qkv[NTOK * 3 * Dd];
__device__ float g_ffn[NTOK * DFFd];

// ---------------------------------------------------------------------------
// tf32 helpers
// ---------------------------------------------------------------------------
__device__ __forceinline__ unsigned f2tf(float f) {
    unsigned u;
    asm("cvt.rna.tf32.f32 %0, %1;" : "=r"(u) : "f"(f));
    return u;
}

__device__ __forceinline__ void mma_tf32(
    float c[4], unsigned a0, unsigned a1, unsigned a2, unsigned a3,
    unsigned b0, unsigned b1)
{
    asm volatile(
        "mma.sync.aligned.m16n8k8.row.col.f32.tf32.tf32.f32 "
        "{%0,%1,%2,%3}, {%4,%5,%6,%7}, {%8,%9}, {%0,%1,%2,%3};"
        : "+f"(c[0]), "+f"(c[1]), "+f"(c[2]), "+f"(c[3])
        : "r"(a0), "r"(a1), "r"(a2), "r"(a3), "r"(b0), "r"(b1));
}

__device__ __forceinline__ uint4 tf4(float4 v) {
    return make_uint4(f2tf(v.x), f2tf(v.y), f2tf(v.z), f2tf(v.w));
}

// ---------------------------------------------------------------------------
// Tensor-core NT GEMM: C[N,M] = A[N,K] @ W[M,K]^T + bias[M]  (row-major)
// Block: 256 thr = 8 warps (2m x 4n), tile 128x128, K-tile 16, double-buffered.
// Requires rows % 128 == 0, M % 128 == 0, K % 16 == 0.
// grid = (M/128, rows/128)
// ---------------------------------------------------------------------------
__global__ __launch_bounds__(256) void gemm_tc(
    const float* __restrict__ A, int lda,
    const float* __restrict__ W, int ldw,
    const float* __restrict__ bias,
    float* __restrict__ C, int ldc,
    int K, int relu)
{
    __shared__ unsigned As[2][128 * BKST];
    __shared__ unsigned Bs[2][128 * BKST];
    const int tid = threadIdx.x, lane = tid & 31, wid = tid >> 5;
    const int wm = (wid & 1) << 6, wn = (wid >> 1) << 5;
    const int bm = blockIdx.y << 7, bn = blockIdx.x << 7;
    const int r8 = lane >> 2, l3 = lane & 3;
    const int arow = tid >> 1, acb = (tid & 1) << 3;
    float acc[4][4][4] = {};
    const float* pA = A + (size_t)(bm + arow) * lda + acb;
    const float* pB = W + (size_t)(bn + arow) * ldw + acb;
    float4 ra0 = *(const float4*)pA;
    float4 ra1 = *(const float4*)(pA + 4);
    float4 rb0 = *(const float4*)pB;
    float4 rb1 = *(const float4*)(pB + 4);
    *(uint4*)&As[0][arow * BKST + acb]     = tf4(ra0);
    *(uint4*)&As[0][arow * BKST + acb + 4] = tf4(ra1);
    *(uint4*)&Bs[0][arow * BKST + acb]     = tf4(rb0);
    *(uint4*)&Bs[0][arow * BKST + acb + 4] = tf4(rb1);
    __syncthreads();
    const int T = K >> 4;
    for (int t = 0; t < T; t++) {
        const unsigned* Abuf = As[t & 1];
        const unsigned* Bbuf = Bs[t & 1];
        if (t + 1 < T) {
            pA += 16; pB += 16;
            ra0 = *(const float4*)pA;
            ra1 = *(const float4*)(pA + 4);
            rb0 = *(const float4*)pB;
            rb1 = *(const float4*)(pB + 4);
        }
        #pragma unroll
        for (int kk = 0; kk < 16; kk += 8) {
            unsigned af[4][4], bf[4][2];
            const int c = kk + l3;
            #pragma unroll
            for (int mt = 0; mt < 4; mt++) {
                const int r = wm + mt * 16 + r8;
                af[mt][0] = Abuf[r * BKST + c];
                af[mt][1] = Abuf[(r + 8) * BKST + c];
                af[mt][2] = Abuf[r * BKST + c + 4];
                af[mt][3] = Abuf[(r + 8) * BKST + c + 4];
            }
            #pragma unroll
            for (int nt = 0; nt < 4; nt++) {
                const int n = wn + nt * 8 + r8;
                bf[nt][0] = Bbuf[n * BKST + c];
                bf[nt][1] = Bbuf[n * BKST + c + 4];
            }
            #pragma unroll
            for (int mt = 0; mt < 4; mt++)
                #pragma unroll
                for (int nt = 0; nt < 4; nt++)
                    mma_tf32(acc[mt][nt], af[mt][0], af[mt][1], af[mt][2], af[mt][3],
                             bf[nt][0], bf[nt][1]);
        }
        if (t + 1 < T) {
            unsigned* Anxt = As[(t + 1) & 1];
            unsigned* Bnxt = Bs[(t + 1) & 1];
            *(uint4*)&Anxt[arow * BKST + acb]     = tf4(ra0);
            *(uint4*)&Anxt[arow * BKST + acb + 4] = tf4(ra1);
            *(uint4*)&Bnxt[arow * BKST + acb]     = tf4(rb0);
            *(uint4*)&Bnxt[arow * BKST + acb + 4] = tf4(rb1);
            __syncthreads();
        }
    }
    #pragma unroll
    for (int mt = 0; mt < 4; mt++) {
        const int row = bm + wm + mt * 16 + r8;
        #pragma unroll
        for (int nt = 0; nt < 4; nt++) {
            const int col = bn + wn + nt * 8 + (l3 << 1);
            const float bx = bias[col], by = bias[col + 1];
            float v0 = acc[mt][nt][0] + bx, v1 = acc[mt][nt][1] + by;
            float v2 = acc[mt][nt][2] + bx, v3 = acc[mt][nt][3] + by;
            if (relu) {
                v0 = fmaxf(v0, 0.f); v1 = fmaxf(v1, 0.f);
                v2 = fmaxf(v2, 0.f); v3 = fmaxf(v3, 0.f);
            }
            float2 w0 = {v0, v1}, w1 = {v2, v3};
            *(float2*)&C[(size_t)row * ldc + col]       = w0;
            *(float2*)&C[(size_t)(row + 8) * ldc + col] = w1;
        }
    }
}

// ---------------------------------------------------------------------------
// Fused flash attention: per (128-q tile, window-head), online softmax.
// grid = (7, 96), block 256 (8 warps 4m x 2n). Dynamic SMEM = FA_BYTES.
// ---------------------------------------------------------------------------
__global__ __launch_bounds__(256) void flash_attn(
    const float* __restrict__ qkv, float* __restrict__ attn, int shifted)
{
    extern __shared__ unsigned sm[];
    unsigned* Qs = sm + FA_QS;
    unsigned* Ps = sm + FA_PS;
    unsigned* KV = sm + FA_KV;
    float* redM = (float*)(sm + FA_REDM);
    float* redL = (float*)(sm + FA_REDL);

    const int wh = blockIdx.y, w = wh >> 3, h = wh & 7;
    const int bm = blockIdx.x << 7;
    const int tid = threadIdx.x, lane = tid & 31, wid = tid >> 5;
    const int wm = (wid & 3) << 5, wn = (wid >> 2) << 5;
    const int wnIdx = wid >> 2;
    const int r8 = lane >> 2, l3 = lane & 3;
    const float* base = qkv + (size_t)w * Ss * QKVLD + h * HDd;
    const float4 z4 = {0.f, 0.f, 0.f, 0.f};
    const bool maskw = (shifted != 0) && ((w % NWw) == 0);

    // Load Q tile [128 x 64] into Qs (tf32, stride QPST)
    {
        const int cc = (tid & 3) << 2;
        #pragma unroll
        for (int i = 0; i < 2; i++) {
            const int r = (tid >> 2) + (i << 6);
            const int q = bm + r;
            const float* p = base + (size_t)q * QKVLD + cc;
            #pragma unroll
            for (int j = 0; j < 4; j++) {
                float4 v = (q < Ss) ? *(const float4*)(p + 16 * j) : z4;
                *(uint4*)&Qs[r * QPST + cc + 16 * j] = tf4(v);
            }
        }
    }

    float accO[2][4][4] = {};
    float mst[2][2] = {{-1e30f, -1e30f}, {-1e30f, -1e30f}};
    float lst[2][2] = {{0.f, 0.f}, {0.f, 0.f}};

    for (int kt = 0; kt < 13; kt++) {
        const int k0 = kt << 6;
        __syncthreads();   // protect KV + Ps from previous iteration's MMA reads
        // Load K tile [64 x 64] -> KV (stride QPST)
        {
            const int kr = tid >> 2, cc = (tid & 3) << 2;
            const int gk = k0 + kr;
            const float* p = base + Dd + (size_t)gk * QKVLD + cc;
            #pragma unroll
            for (int j = 0; j < 4; j++) {
                float4 v = (gk < Ss) ? *(const float4*)(p + 16 * j) : z4;
                *(uint4*)&KV[kr * QPST + cc + 16 * j] = tf4(v);
            }
        }
        __syncthreads();

        // S = Q @ K^T
        float s[2][4][4] = {};
        #pragma unroll
        for (int kk = 0; kk < 64; kk += 8) {
            unsigned af[2][4], bf[4][2];
            const int c = kk + l3;
            #pragma unroll
            for (int mt = 0; mt < 2; mt++) {
                const int r = wm + mt * 16 + r8;
                af[mt][0] = Qs[r * QPST + c];
                af[mt][1] = Qs[(r + 8) * QPST + c];
                af[mt][2] = Qs[r * QPST + c + 4];
                af[mt][3] = Qs[(r + 8) * QPST + c + 4];
            }
            #pragma unroll
            for (int nt = 0; nt < 4; nt++) {
                const int n = wn + nt * 8 + r8;
                bf[nt][0] = KV[n * QPST + c];
                bf[nt][1] = KV[n * QPST + c + 4];
            }
            #pragma unroll
            for (int mt = 0; mt < 2; mt++)
                #pragma unroll
                for (int nt = 0; nt < 4; nt++)
                    mma_tf32(s[mt][nt], af[mt][0], af[mt][1], af[mt][2], af[mt][3],
                             bf[nt][0], bf[nt][1]);
        }

        // scale + mask + OOB; local row max
        float lm[2][2] = {{-1e30f, -1e30f}, {-1e30f, -1e30f}};
        #pragma unroll
        for (int mt = 0; mt < 2; mt++) {
            #pragma unroll
            for (int e = 0; e < 4; e++) {
                const int eh = e >> 1;
                const int q = bm + wm + mt * 16 + r8 + eh * 8;
                const int tq = q / FQn;
                #pragma unroll
                for (int nt = 0; nt < 4; nt++) {
                    const int k = k0 + wn + nt * 8 + (l3 << 1) + (e & 1);
                    float v = s[mt][nt][e] * 0.125f;
                    if (maskw) {
                        const int tk = k / FQn;
                        if ((tq < HALFh) != (tk < HALFh)) v -= 1000.0f;
                    }
                    if (k >= Ss) v = -1e30f;
                    s[mt][nt][e] = v;
                    lm[mt][eh] = fmaxf(lm[mt][eh], v);
                }
            }
        }
        // reduce max across lane&3 quad, publish per-warp-col
        #pragma unroll
        for (int mt = 0; mt < 2; mt++)
            #pragma unroll
            for (int eh = 0; eh < 2; eh++) {
                float v = lm[mt][eh];
                v = fmaxf(v, __shfl_xor_sync(0xffffffffu, v, 1));
                v = fmaxf(v, __shfl_xor_sync(0xffffffffu, v, 2));
                lm[mt][eh] = v;
                redM[wnIdx * 128 + wm + mt * 16 + eh * 8 + r8] = v;
            }
        __syncthreads();

        // m_new, alpha, p, local sums; store P; load V; rescale O
        float ls[2][2];
        float mnew[2][2];
        #pragma unroll
        for (int mt = 0; mt < 2; mt++) {
            #pragma unroll
            for (int eh = 0; eh < 2; eh++) {
                const int r = wm + mt * 16 + eh * 8 + r8;
                const float comb = fmaxf(redM[r], redM[128 + r]);
                const float mn = fmaxf(mst[mt][eh], comb);
                mnew[mt][eh] = mn;
                const float alpha = __expf(mst[mt][eh] - mn);
                mst[mt][eh] = mn;
                #pragma unroll
                for (int nt = 0; nt < 4; nt++) {
                    accO[mt][nt][eh * 2]     *= alpha;
                    accO[mt][nt][eh * 2 + 1] *= alpha;
                }
                lst[mt][eh] *= alpha;
                ls[mt][eh] = 0.f;
            }
        }
        #pragma unroll
        for (int mt = 0; mt < 2; mt++) {
            #pragma unroll
            for (int eh = 0; eh < 2; eh++) {
                const int r = wm + mt * 16 + eh * 8 + r8;
                #pragma unroll
                for (int nt = 0; nt < 4; nt++) {
                    const float p0 = __expf(s[mt][nt][eh * 2]     - mnew[mt][eh]);
                    const float p1 = __expf(s[mt][nt][eh * 2 + 1] - mnew[mt][eh]);
                    ls[mt][eh] += p0 + p1;
                    uint2 pp = {f2tf(p0), f2tf(p1)};
                    *(uint2*)&Ps[r * QPST + wn + nt * 8 + (l3 << 1)] = pp;
                }
                float v = ls[mt][eh];
                v += __shfl_xor_sync(0xffffffffu, v, 1);
                v += __shfl_xor_sync(0xffffffffu, v, 2);
                redL[wnIdx * 128 + r] = v;
            }
        }
        // Load V tile [64 x 64] -> KV k-major (stride VST); S-MMA reads done
        {
            const int vk = tid >> 2, cc = (tid & 3) << 2;
            const int gk = k0 + vk;
            const float* p = base + 2 * Dd + (size_t)gk * QKVLD + cc;
            #pragma unroll
            for (int j = 0; j < 4; j++) {
                float4 v = (gk < Ss) ? *(const float4*)(p + 16 * j) : z4;
                *(uint4*)&KV[vk * VST + cc + 16 * j] = tf4(v);
            }
        }
        __syncthreads();   // Ps, redL, V ready

        #pragma unroll
        for (int mt = 0; mt < 2; mt++)
            #pragma unroll
            for (int eh = 0; eh < 2; eh++) {
                const int r = wm + mt * 16 + eh * 8 + r8;
                lst[mt][eh] += redL[r] + redL[128 + r];
            }

        // O += P @ V
        #pragma unroll
        for (int kk = 0; kk < 64; kk += 8) {
            unsigned af[2][4], bf[4][2];
            const int c = kk + l3;
            #pragma unroll
            for (int mt = 0; mt < 2; mt++) {
                const int r = wm + mt * 16 + r8;
                af[mt][0] = Ps[r * QPST + c];
                af[mt][1] = Ps[(r + 8) * QPST + c];
                af[mt][2] = Ps[r * QPST + c + 4];
                af[mt][3] = Ps[(r + 8) * QPST + c + 4];
            }
            #pragma unroll
            for (int nt = 0; nt < 4; nt++) {
                const int n = wn + nt * 8 + r8;
                bf[nt][0] = KV[c * VST + n];
                bf[nt][1] = KV[(c + 4) * VST + n];
            }
            #pragma unroll
            for (int mt = 0; mt < 2; mt++)
                #pragma unroll
                for (int nt = 0; nt < 4; nt++)
                    mma_tf32(accO[mt][nt], af[mt][0], af[mt][1], af[mt][2], af[mt][3],
                             bf[nt][0], bf[nt][1]);
        }
    }

    // Epilogue: O /= l, store to attn
    #pragma unroll
    for (int mt = 0; mt < 2; mt++) {
        #pragma unroll
        for (int eh = 0; eh < 2; eh++) {
            const int q = bm + wm + mt * 16 + eh * 8 + r8;
            if (q >= Ss) continue;
            const float inv = 1.0f / lst[mt][eh];
            #pragma unroll
            for (int nt = 0; nt < 4; nt++) {
                const int col = wn + nt * 8 + (l3 << 1);
                float2 o2 = {accO[mt][nt][eh * 2] * inv, accO[mt][nt][eh * 2 + 1] * inv};
                *(float2*)&attn[(size_t)(w * Ss + q) * Dd + h * HDd + col] = o2;
            }
        }
    }
}

// ---------------------------------------------------------------------------
// Window gather with roll: xw[w*S+s] = x[token(w,s,shift)]
// ---------------------------------------------------------------------------
__global__ __launch_bounds__(256) void gather_win(
    const float* __restrict__ x, float* __restrict__ xw, int shift)
{
    const int idx = blockIdx.x * 256 + threadIdx.x;
    const int row = idx >> 7;
    const int c = idx & 127;
    const int w = row / Ss, sidx = row % Ss;
    const int b = w / NWw, nw = w % NWw;
    const int tl = sidx / FQn, fq = sidx % FQn;
    int t = nw * WSZw + tl - shift;
    if (t < 0) t += Tt;
    const size_t n = (size_t)(b * Tt + t) * FQn + fq;
    ((float4*)xw)[(size_t)row * 128 + c] = ((const float4*)x)[n * 128 + c];
}

// ---------------------------------------------------------------------------
// dst[row'] = LayerNorm(xa[row] + xb[row]) * gs + gb
// ---------------------------------------------------------------------------
__global__ __launch_bounds__(256) void add_ln(
    const float* __restrict__ xa, const float* __restrict__ xb,
    const float* __restrict__ gs, const float* __restrict__ gb,
    float* __restrict__ dst, int scatter, int shift)
{
    const int row = blockIdx.x;
    const int tid = threadIdx.x;
    const float* pa = xa + (size_t)row * Dd;
    const float* pb = xb + (size_t)row * Dd;
    const float v0 = pa[tid] + pb[tid];
    const float v1 = pa[tid + 256] + pb[tid + 256];
    __shared__ float red1[8];
    __shared__ float red2[8];
    float s = v0 + v1;
    #pragma unroll
    for (int o = 16; o > 0; o >>= 1) s += __shfl_xor_sync(0xffffffffu, s, o);
    if ((tid & 31) == 0) red1[tid >> 5] = s;
    __syncthreads();
    const float mu = (red1[0] + red1[1] + red1[2] + red1[3] +
                      red1[4] + red1[5] + red1[6] + red1[7]) * (1.0f / Dd);
    const float d0 = v0 - mu, d1 = v1 - mu;
    float ss = d0 * d0 + d1 * d1;
    #pragma unroll
    for (int o = 16; o > 0; o >>= 1) ss += __shfl_xor_sync(0xffffffffu, ss, o);
    if ((tid & 31) == 0) red2[tid >> 5] = ss;
    __syncthreads();
    const float var = (red2[0] + red2[1] + red2[2] + red2[3] +
                       red2[4] + red2[5] + red2[6] + red2[7]) * (1.0f / Dd);
    const float rstd = rsqrtf(var + 1e-5f);
    size_t drow = row;
    if (scatter) {
        const int w = row / Ss, sidx = row % Ss;
        const int b = w / NWw, nw = w % NWw;
        const int tl = sidx / FQn, fq = sidx % FQn;
        int t = nw * WSZw + tl - shift;
        if (t < 0) t += Tt;
        drow = (size_t)(b * Tt + t) * FQn + fq;
    }
    float* pd = dst + drow * Dd;
    pd[tid]       = d0 * rstd * gs[tid]       + gb[tid];
    pd[tid + 256] = d1 * rstd * gs[tid + 256] + gb[tid + 256];
}

// ---------------------------------------------------------------------------
extern "C" void kernel_launch(void* const* d_in, const int* in_sizes, int n_in,
                              void* d_out, int out_size)
{
    const float* fqin = (const float*)d_in[0];
    const float* Wp   = (const float*)d_in[1];
    const float* bp   = (const float*)d_in[2];
    const float* Wqkv = (const float*)d_in[3];
    const float* bqkv = (const float*)d_in[4];
    const float* Wo   = (const float*)d_in[5];
    const float* bo   = (const float*)d_in[6];
    const float* ln1s = (const float*)d_in[7];
    const float* ln1b = (const float*)d_in[8];
    const float* W1   = (const float*)d_in[9];
    const float* b1   = (const float*)d_in[10];
    const float* W2   = (const float*)d_in[11];
    const float* b2   = (const float*)d_in[12];
    const float* ln2s = (const float*)d_in[13];
    const float* ln2b = (const float*)d_in[14];
    float* out = (float*)d_out;

    float *x, *xw, *tmp, *attn, *qkv, *ffn;
    cudaGetSymbolAddress((void**)&x,    g_x);
    cudaGetSymbolAddress((void**)&xw,   g_xw);
    cudaGetSymbolAddress((void**)&tmp,  g_tmp);
    cudaGetSymbolAddress((void**)&attn, g_attn);
    cudaGetSymbolAddress((void**)&qkv,  g_qkv);
    cudaGetSymbolAddress((void**)&ffn,  g_ffn);

    cudaFuncSetAttribute(flash_attn,
                         cudaFuncAttributeMaxDynamicSharedMemorySize, FA_BYTES);

    // Input projection: x = fq @ Wp^T + bp
    gemm_tc<<<dim3(Dd / 128, NTOK / 128), 256>>>(fqin, Dd, Wp, Dd, bp, x, Dd, Dd, 0);

    for (int i = 0; i < Ll; i++) {
        const int shifted = i & 1;
        const int shift = shifted ? HALFh : 0;

        // window gather (with roll for shifted layers)
        gather_win<<<NTOK * 128 / 256, 256>>>(x, xw, shift);

        // QKV projection
        gemm_tc<<<dim3(3 * Dd / 128, NTOK / 128), 256>>>(
            xw, Dd, Wqkv + (size_t)i * 3 * Dd * Dd, Dd,
            bqkv + (size_t)i * 3 * Dd, qkv, 3 * Dd, Dd, 0);

        // fused attention (scores + mask + softmax + AV)
        flash_attn<<<dim3(7, WHn), 256, FA_BYTES>>>(qkv, attn, shifted);

        // output projection
        gemm_tc<<<dim3(Dd / 128, NTOK / 128), 256>>>(
            attn, Dd, Wo + (size_t)i * Dd * Dd, Dd,
            bo + (size_t)i * Dd, tmp, Dd, Dd, 0);

        // residual + LN1, scatter back (inverse roll)
        add_ln<<<NTOK, 256>>>(xw, tmp, ln1s + (size_t)i * Dd, ln1b + (size_t)i * Dd,
                              x, 1, shift);

        // FFN
        gemm_tc<<<dim3(DFFd / 128, NTOK / 128), 256>>>(
            x, Dd, W1 + (size_t)i * DFFd * Dd, Dd,
            b1 + (size_t)i * DFFd, ffn, DFFd, Dd, 1);
        gemm_tc<<<dim3(Dd / 128, NTOK / 128), 256>>>(
            ffn, DFFd, W2 + (size_t)i * Dd * DFFd, DFFd,
            b2 + (size_t)i * Dd, tmp, Dd, DFFd, 0);

        // residual + LN2 (final layer writes straight to d_out)
        add_ln<<<NTOK, 256>>>(x, tmp, ln2s + (size_t)i * Dd, ln2b + (size_t)i * Dd,
                              (i == Ll - 1) ? out : x, 0, 0);
    }
    (void)in_sizes; (void)n_in; (void)out_size;
}

// round 9
// speedup vs baseline: 3.3080x; 1.0815x over previous
#include <cuda_runtime.h>
#include <cstdint>

// Problem constants
#define Bb    2
#define Tt    48
#define FQn   100
#define Dd    512
#define Hh    8
#define HDd   64
#define DFFd  2048
#define Ll    6
#define WSZw  8
#define NWw   6          // windows per batch item (T/WSZ)
#define NWIN  12         // B * NWw
#define Ss    800        // WSZ * FQ
#define HALFh 4          // ceil(WSZ/2)
#define NTOK  9600       // B*T*FQ
#define WHn   96         // NWIN * H
#define QKVLD 1536       // 3*D row stride in qkv buffer

#define GST 24           // gemm SMEM k-stride (16 perm + 8 pad; 24*r8+2*l3 tiles banks)
#define QPST 68          // SMEM stride for 64-wide q/k/p tiles (≡4 mod 32)
#define VST 72           // SMEM stride for k-major V tile (≡8 mod 32)

// Flash SMEM layout (words)
#define FA_QS   0
#define FA_PS   (128 * QPST)
#define FA_KV   (FA_PS + 128 * QPST)
#define FA_REDM (FA_KV + 64 * VST)
#define FA_REDL (FA_REDM + 256)
#define FA_WORDS (FA_REDL + 256)
#define FA_BYTES (FA_WORDS * 4)

// Scratch (device globals: allocation-guard safe)
__device__ float g_x[NTOK * Dd];
__device__ float g_xw[NTOK * Dd];
__device__ float g_tmp[NTOK * Dd];
__device__ float g_attn[NTOK * Dd];
__device__ float g_qkv[NTOK * 3 * Dd];
__device__ float g_ffn[NTOK * DFFd];

// ---------------------------------------------------------------------------
// tf32 helpers
// ---------------------------------------------------------------------------
__device__ __forceinline__ unsigned f2tf(float f) {
    unsigned u;
    asm("cvt.rna.tf32.f32 %0, %1;" : "=r"(u) : "f"(f));
    return u;
}

__device__ __forceinline__ void mma_tf32(
    float c[4], unsigned a0, unsigned a1, unsigned a2, unsigned a3,
    unsigned b0, unsigned b1)
{
    asm volatile(
        "mma.sync.aligned.m16n8k8.row.col.f32.tf32.tf32.f32 "
        "{%0,%1,%2,%3}, {%4,%5,%6,%7}, {%8,%9}, {%0,%1,%2,%3};"
        : "+f"(c[0]), "+f"(c[1]), "+f"(c[2]), "+f"(c[3])
        : "r"(a0), "r"(a1), "r"(a2), "r"(a3), "r"(b0), "r"(b1));
}

__device__ __forceinline__ uint4 tf4(float4 v) {
    return make_uint4(f2tf(v.x), f2tf(v.y), f2tf(v.z), f2tf(v.w));
}

// Store one 16-k row slab (8 words from ra0/ra1 = k in [g*8, g*8+8)) into the
// paired layout: word k -> (k&8) + 2*(k&3) + ((k>>2)&1).  g = 0/1 selects slab.
__device__ __forceinline__ void store_paired(
    unsigned* dst, float4 ra0, float4 ra1)
{
    *(uint2*)&dst[0] = make_uint2(f2tf(ra0.x), f2tf(ra1.x));
    *(uint2*)&dst[2] = make_uint2(f2tf(ra0.y), f2tf(ra1.y));
    *(uint2*)&dst[4] = make_uint2(f2tf(ra0.z), f2tf(ra1.z));
    *(uint2*)&dst[6] = make_uint2(f2tf(ra0.w), f2tf(ra1.w));
}

// ---------------------------------------------------------------------------
// Tensor-core NT GEMM: C[N,M] = A[N,K] @ W[M,K]^T + bias[M]  (row-major)
// Block: 256 thr = 8 warps (2m x 4n), tile 128x128, K-tile 16, double-buffered.
// Paired SMEM layout: fragment (c, c+4) adjacent -> LDS.64 loads.
// grid = (M/128, rows/128)
// ---------------------------------------------------------------------------
__global__ __launch_bounds__(256) void gemm_tc(
    const float* __restrict__ A, int lda,
    const float* __restrict__ W, int ldw,
    const float* __restrict__ bias,
    float* __restrict__ C, int ldc,
    int K, int relu)
{
    __shared__ unsigned As[2][128 * GST];
    __shared__ unsigned Bs[2][128 * GST];
    const int tid = threadIdx.x, lane = tid & 31, wid = tid >> 5;
    const int wm = (wid & 1) << 6, wn = (wid >> 1) << 5;
    const int bm = blockIdx.y << 7, bn = blockIdx.x << 7;
    const int r8 = lane >> 2, l3 = lane & 3;
    const int arow = tid >> 1, acb = (tid & 1) << 3;   // 8-word GMEM slab
    float acc[4][4][4] = {};
    const float* pA = A + (size_t)(bm + arow) * lda + acb;
    const float* pB = W + (size_t)(bn + arow) * ldw + acb;
    float4 ra0 = *(const float4*)pA;
    float4 ra1 = *(const float4*)(pA + 4);
    float4 rb0 = *(const float4*)pB;
    float4 rb1 = *(const float4*)(pB + 4);
    store_paired(&As[0][arow * GST + acb], ra0, ra1);
    store_paired(&Bs[0][arow * GST + acb], rb0, rb1);
    __syncthreads();
    const int T = K >> 4;
    for (int t = 0; t < T; t++) {
        const unsigned* Abuf = As[t & 1];
        const unsigned* Bbuf = Bs[t & 1];
        if (t + 1 < T) {
            pA += 16; pB += 16;
            ra0 = *(const float4*)pA;
            ra1 = *(const float4*)(pA + 4);
            rb0 = *(const float4*)pB;
            rb1 = *(const float4*)(pB + 4);
        }
        #pragma unroll
        for (int kk = 0; kk < 16; kk += 8) {
            uint2 alo[4], ahi[4], bfp[4];
            const int co = kk + (l3 << 1);
            #pragma unroll
            for (int mt = 0; mt < 4; mt++) {
                const int r = wm + mt * 16 + r8;
                alo[mt] = *(const uint2*)&Abuf[r * GST + co];
                ahi[mt] = *(const uint2*)&Abuf[(r + 8) * GST + co];
            }
            #pragma unroll
            for (int nt = 0; nt < 4; nt++) {
                const int n = wn + nt * 8 + r8;
                bfp[nt] = *(const uint2*)&Bbuf[n * GST + co];
            }
            #pragma unroll
            for (int mt = 0; mt < 4; mt++)
                #pragma unroll
                for (int nt = 0; nt < 4; nt++)
                    mma_tf32(acc[mt][nt], alo[mt].x, ahi[mt].x, alo[mt].y, ahi[mt].y,
                             bfp[nt].x, bfp[nt].y);
        }
        if (t + 1 < T) {
            unsigned* Anxt = As[(t + 1) & 1];
            unsigned* Bnxt = Bs[(t + 1) & 1];
            store_paired(&Anxt[arow * GST + acb], ra0, ra1);
            store_paired(&Bnxt[arow * GST + acb], rb0, rb1);
            __syncthreads();
        }
    }
    #pragma unroll
    for (int mt = 0; mt < 4; mt++) {
        const int row = bm + wm + mt * 16 + r8;
        #pragma unroll
        for (int nt = 0; nt < 4; nt++) {
            const int col = bn + wn + nt * 8 + (l3 << 1);
            const float bx = bias[col], by = bias[col + 1];
            float v0 = acc[mt][nt][0] + bx, v1 = acc[mt][nt][1] + by;
            float v2 = acc[mt][nt][2] + bx, v3 = acc[mt][nt][3] + by;
            if (relu) {
                v0 = fmaxf(v0, 0.f); v1 = fmaxf(v1, 0.f);
                v2 = fmaxf(v2, 0.f); v3 = fmaxf(v3, 0.f);
            }
            float2 w0 = {v0, v1}, w1 = {v2, v3};
            *(float2*)&C[(size_t)row * ldc + col]       = w0;
            *(float2*)&C[(size_t)(row + 8) * ldc + col] = w1;
        }
    }
}

// ---------------------------------------------------------------------------
// Fused flash attention: per (128-q tile, window-head), online softmax.
// grid = (7, 96), block 256 (8 warps 4m x 2n). Dynamic SMEM = FA_BYTES.
// ---------------------------------------------------------------------------
__global__ __launch_bounds__(256) void flash_attn(
    const float* __restrict__ qkv, float* __restrict__ attn, int shifted)
{
    extern __shared__ unsigned sm[];
    unsigned* Qs = sm + FA_QS;
    unsigned* Ps = sm + FA_PS;
    unsigned* KV = sm + FA_KV;
    float* redM = (float*)(sm + FA_REDM);
    float* redL = (float*)(sm + FA_REDL);

    const int wh = blockIdx.y, w = wh >> 3, h = wh & 7;
    const int bm = blockIdx.x << 7;
    const int tid = threadIdx.x, lane = tid & 31, wid = tid >> 5;
    const int wm = (wid & 3) << 5, wn = (wid >> 2) << 5;
    const int wnIdx = wid >> 2;
    const int r8 = lane >> 2, l3 = lane & 3;
    const float* base = qkv + (size_t)w * Ss * QKVLD + h * HDd;
    const float4 z4 = {0.f, 0.f, 0.f, 0.f};
    const bool maskw = (shifted != 0) && ((w % NWw) == 0);

    // Load Q tile [128 x 64] into Qs (tf32, stride QPST)
    {
        const int cc = (tid & 3) << 2;
        #pragma unroll
        for (int i = 0; i < 2; i++) {
            const int r = (tid >> 2) + (i << 6);
            const int q = bm + r;
            const float* p = base + (size_t)q * QKVLD + cc;
            #pragma unroll
            for (int j = 0; j < 4; j++) {
                float4 v = (q < Ss) ? *(const float4*)(p + 16 * j) : z4;
                *(uint4*)&Qs[r * QPST + cc + 16 * j] = tf4(v);
            }
        }
    }

    float accO[2][4][4] = {};
    float mst[2][2] = {{-1e30f, -1e30f}, {-1e30f, -1e30f}};
    float lst[2][2] = {{0.f, 0.f}, {0.f, 0.f}};

    for (int kt = 0; kt < 13; kt++) {
        const int k0 = kt << 6;
        __syncthreads();   // protect KV + Ps from previous iteration's MMA reads
        // Load K tile [64 x 64] -> KV (stride QPST)
        {
            const int kr = tid >> 2, cc = (tid & 3) << 2;
            const int gk = k0 + kr;
            const float* p = base + Dd + (size_t)gk * QKVLD + cc;
            #pragma unroll
            for (int j = 0; j < 4; j++) {
                float4 v = (gk < Ss) ? *(const float4*)(p + 16 * j) : z4;
                *(uint4*)&KV[kr * QPST + cc + 16 * j] = tf4(v);
            }
        }
        __syncthreads();

        // S = Q @ K^T
        float s[2][4][4] = {};
        #pragma unroll
        for (int kk = 0; kk < 64; kk += 8) {
            unsigned af[2][4], bf[4][2];
            const int c = kk + l3;
            #pragma unroll
            for (int mt = 0; mt < 2; mt++) {
                const int r = wm + mt * 16 + r8;
                af[mt][0] = Qs[r * QPST + c];
                af[mt][1] = Qs[(r + 8) * QPST + c];
                af[mt][2] = Qs[r * QPST + c + 4];
                af[mt][3] = Qs[(r + 8) * QPST + c + 4];
            }
            #pragma unroll
            for (int nt = 0; nt < 4; nt++) {
                const int n = wn + nt * 8 + r8;
                bf[nt][0] = KV[n * QPST + c];
                bf[nt][1] = KV[n * QPST + c + 4];
            }
            #pragma unroll
            for (int mt = 0; mt < 2; mt++)
                #pragma unroll
                for (int nt = 0; nt < 4; nt++)
                    mma_tf32(s[mt][nt], af[mt][0], af[mt][1], af[mt][2], af[mt][3],
                             bf[nt][0], bf[nt][1]);
        }

        // scale + mask + OOB; local row max
        float lm[2][2] = {{-1e30f, -1e30f}, {-1e30f, -1e30f}};
        #pragma unroll
        for (int mt = 0; mt < 2; mt++) {
            #pragma unroll
            for (int e = 0; e < 4; e++) {
                const int eh = e >> 1;
                const int q = bm + wm + mt * 16 + r8 + eh * 8;
                const int tq = q / FQn;
                #pragma unroll
                for (int nt = 0; nt < 4; nt++) {
                    const int k = k0 + wn + nt * 8 + (l3 << 1) + (e & 1);
                    float v = s[mt][nt][e] * 0.125f;
                    if (maskw) {
                        const int tk = k / FQn;
                        if ((tq < HALFh) != (tk < HALFh)) v -= 1000.0f;
                    }
                    if (k >= Ss) v = -1e30f;
                    s[mt][nt][e] = v;
                    lm[mt][eh] = fmaxf(lm[mt][eh], v);
                }
            }
        }
        // reduce max across lane&3 quad, publish per-warp-col
        #pragma unroll
        for (int mt = 0; mt < 2; mt++)
            #pragma unroll
            for (int eh = 0; eh < 2; eh++) {
                float v = lm[mt][eh];
                v = fmaxf(v, __shfl_xor_sync(0xffffffffu, v, 1));
                v = fmaxf(v, __shfl_xor_sync(0xffffffffu, v, 2));
                lm[mt][eh] = v;
                redM[wnIdx * 128 + wm + mt * 16 + eh * 8 + r8] = v;
            }
        __syncthreads();

        // m_new, alpha, p, local sums; store P; load V; rescale O
        float ls[2][2];
        float mnew[2][2];
        #pragma unroll
        for (int mt = 0; mt < 2; mt++) {
            #pragma unroll
            for (int eh = 0; eh < 2; eh++) {
                const int r = wm + mt * 16 + eh * 8 + r8;
                const float comb = fmaxf(redM[r], redM[128 + r]);
                const float mn = fmaxf(mst[mt][eh], comb);
                mnew[mt][eh] = mn;
                const float alpha = __expf(mst[mt][eh] - mn);
                mst[mt][eh] = mn;
                #pragma unroll
                for (int nt = 0; nt < 4; nt++) {
                    accO[mt][nt][eh * 2]     *= alpha;
                    accO[mt][nt][eh * 2 + 1] *= alpha;
                }
                lst[mt][eh] *= alpha;
                ls[mt][eh] = 0.f;
            }
        }
        #pragma unroll
        for (int mt = 0; mt < 2; mt++) {
            #pragma unroll
            for (int eh = 0; eh < 2; eh++) {
                const int r = wm + mt * 16 + eh * 8 + r8;
                #pragma unroll
                for (int nt = 0; nt < 4; nt++) {
                    const float p0 = __expf(s[mt][nt][eh * 2]     - mnew[mt][eh]);
                    const float p1 = __expf(s[mt][nt][eh * 2 + 1] - mnew[mt][eh]);
                    ls[mt][eh] += p0 + p1;
                    uint2 pp = {f2tf(p0), f2tf(p1)};
                    *(uint2*)&Ps[r * QPST + wn + nt * 8 + (l3 << 1)] = pp;
                }
                float v = ls[mt][eh];
                v += __shfl_xor_sync(0xffffffffu, v, 1);
                v += __shfl_xor_sync(0xffffffffu, v, 2);
                redL[wnIdx * 128 + r] = v;
            }
        }
        // Load V tile [64 x 64] -> KV k-major (stride VST); S-MMA reads done
        {
            const int vk = tid >> 2, cc = (tid & 3) << 2;
            const int gk = k0 + vk;
            const float* p = base + 2 * Dd + (size_t)gk * QKVLD + cc;
            #pragma unroll
            for (int j = 0; j < 4; j++) {
                float4 v = (gk < Ss) ? *(const float4*)(p + 16 * j) : z4;
                *(uint4*)&KV[vk * VST + cc + 16 * j] = tf4(v);
            }
        }
        __syncthreads();   // Ps, redL, V ready

        #pragma unroll
        for (int mt = 0; mt < 2; mt++)
            #pragma unroll
            for (int eh = 0; eh < 2; eh++) {
                const int r = wm + mt * 16 + eh * 8 + r8;
                lst[mt][eh] += redL[r] + redL[128 + r];
            }

        // O += P @ V
        #pragma unroll
        for (int kk = 0; kk < 64; kk += 8) {
            unsigned af[2][4], bf[4][2];
            const int c = kk + l3;
            #pragma unroll
            for (int mt = 0; mt < 2; mt++) {
                const int r = wm + mt * 16 + r8;
                af[mt][0] = Ps[r * QPST + c];
                af[mt][1] = Ps[(r + 8) * QPST + c];
                af[mt][2] = Ps[r * QPST + c + 4];
                af[mt][3] = Ps[(r + 8) * QPST + c + 4];
            }
            #pragma unroll
            for (int nt = 0; nt < 4; nt++) {
                const int n = wn + nt * 8 + r8;
                bf[nt][0] = KV[c * VST + n];
                bf[nt][1] = KV[(c + 4) * VST + n];
            }
            #pragma unroll
            for (int mt = 0; mt < 2; mt++)
                #pragma unroll
                for (int nt = 0; nt < 4; nt++)
                    mma_tf32(accO[mt][nt], af[mt][0], af[mt][1], af[mt][2], af[mt][3],
                             bf[nt][0], bf[nt][1]);
        }
    }

    // Epilogue: O /= l, store to attn
    #pragma unroll
    for (int mt = 0; mt < 2; mt++) {
        #pragma unroll
        for (int eh = 0; eh < 2; eh++) {
            const int q = bm + wm + mt * 16 + eh * 8 + r8;
            if (q >= Ss) continue;
            const float inv = 1.0f / lst[mt][eh];
            #pragma unroll
            for (int nt = 0; nt < 4; nt++) {
                const int col = wn + nt * 8 + (l3 << 1);
                float2 o2 = {accO[mt][nt][eh * 2] * inv, accO[mt][nt][eh * 2 + 1] * inv};
                *(float2*)&attn[(size_t)(w * Ss + q) * Dd + h * HDd + col] = o2;
            }
        }
    }
}

// ---------------------------------------------------------------------------
// Window gather with roll: xw[w*S+s] = x[token(w,s,shift)]
// ---------------------------------------------------------------------------
__global__ __launch_bounds__(256) void gather_win(
    const float* __restrict__ x, float* __restrict__ xw, int shift)
{
    const int idx = blockIdx.x * 256 + threadIdx.x;
    const int row = idx >> 7;
    const int c = idx & 127;
    const int w = row / Ss, sidx = row % Ss;
    const int b = w / NWw, nw = w % NWw;
    const int tl = sidx / FQn, fq = sidx % FQn;
    int t = nw * WSZw + tl - shift;
    if (t < 0) t += Tt;
    const size_t n = (size_t)(b * Tt + t) * FQn + fq;
    ((float4*)xw)[(size_t)row * 128 + c] = ((const float4*)x)[n * 128 + c];
}

// ---------------------------------------------------------------------------
// dst[row'] = LayerNorm(xa[row] + xb[row]) * gs + gb
// ---------------------------------------------------------------------------
__global__ __launch_bounds__(256) void add_ln(
    const float* __restrict__ xa, const float* __restrict__ xb,
    const float* __restrict__ gs, const float* __restrict__ gb,
    float* __restrict__ dst, int scatter, int shift)
{
    const int row = blockIdx.x;
    const int tid = threadIdx.x;
    const float* pa = xa + (size_t)row * Dd;
    const float* pb = xb + (size_t)row * Dd;
    const float v0 = pa[tid] + pb[tid];
    const float v1 = pa[tid + 256] + pb[tid + 256];
    __shared__ float red1[8];
    __shared__ float red2[8];
    float s = v0 + v1;
    #pragma unroll
    for (int o = 16; o > 0; o >>= 1) s += __shfl_xor_sync(0xffffffffu, s, o);
    if ((tid & 31) == 0) red1[tid >> 5] = s;
    __syncthreads();
    const float mu = (red1[0] + red1[1] + red1[2] + red1[3] +
                      red1[4] + red1[5] + red1[6] + red1[7]) * (1.0f / Dd);
    const float d0 = v0 - mu, d1 = v1 - mu;
    float ss = d0 * d0 + d1 * d1;
    #pragma unroll
    for (int o = 16; o > 0; o >>= 1) ss += __shfl_xor_sync(0xffffffffu, ss, o);
    if ((tid & 31) == 0) red2[tid >> 5] = ss;
    __syncthreads();
    const float var = (red2[0] + red2[1] + red2[2] + red2[3] +
                       red2[4] + red2[5] + red2[6] + red2[7]) * (1.0f / Dd);
    const float rstd = rsqrtf(var + 1e-5f);
    size_t drow = row;
    if (scatter) {
        const int w = row / Ss, sidx = row % Ss;
        const int b = w / NWw, nw = w % NWw;
        const int tl = sidx / FQn, fq = sidx % FQn;
        int t = nw * WSZw + tl - shift;
        if (t < 0) t += Tt;
        drow = (size_t)(b * Tt + t) * FQn + fq;
    }
    float* pd = dst + drow * Dd;
    pd[tid]       = d0 * rstd * gs[tid]       + gb[tid];
    pd[tid + 256] = d1 * rstd * gs[tid + 256] + gb[tid + 256];
}

// ---------------------------------------------------------------------------
extern "C" void kernel_launch(void* const* d_in, const int* in_sizes, int n_in,
                              void* d_out, int out_size)
{
    const float* fqin = (const float*)d_in[0];
    const float* Wp   = (const float*)d_in[1];
    const float* bp   = (const float*)d_in[2];
    const float* Wqkv = (const float*)d_in[3];
    const float* bqkv = (const float*)d_in[4];
    const float* Wo   = (const float*)d_in[5];
    const float* bo   = (const float*)d_in[6];
    const float* ln1s = (const float*)d_in[7];
    const float* ln1b = (const float*)d_in[8];
    const float* W1   = (const float*)d_in[9];
    const float* b1   = (const float*)d_in[10];
    const float* W2   = (const float*)d_in[11];
    const float* b2   = (const float*)d_in[12];
    const float* ln2s = (const float*)d_in[13];
    const float* ln2b = (const float*)d_in[14];
    float* out = (float*)d_out;

    float *x, *xw, *tmp, *attn, *qkv, *ffn;
    cudaGetSymbolAddress((void**)&x,    g_x);
    cudaGetSymbolAddress((void**)&xw,   g_xw);
    cudaGetSymbolAddress((void**)&tmp,  g_tmp);
    cudaGetSymbolAddress((void**)&attn, g_attn);
    cudaGetSymbolAddress((void**)&qkv,  g_qkv);
    cudaGetSymbolAddress((void**)&ffn,  g_ffn);

    cudaFuncSetAttribute(flash_attn,
                         cudaFuncAttributeMaxDynamicSharedMemorySize, FA_BYTES);

    // Input projection: x = fq @ Wp^T + bp
    gemm_tc<<<dim3(Dd / 128, NTOK / 128), 256>>>(fqin, Dd, Wp, Dd, bp, x, Dd, Dd, 0);

    for (int i = 0; i < Ll; i++) {
        const int shifted = i & 1;
        const int shift = shifted ? HALFh : 0;

        // window gather (with roll for shifted layers)
        gather_win<<<NTOK * 128 / 256, 256>>>(x, xw, shift);

        // QKV projection
        gemm_tc<<<dim3(3 * Dd / 128, NTOK / 128), 256>>>(
            xw, Dd, Wqkv + (size_t)i * 3 * Dd * Dd, Dd,
            bqkv + (size_t)i * 3 * Dd, qkv, 3 * Dd, Dd, 0);

        // fused attention (scores + mask + softmax + AV)
        flash_attn<<<dim3(7, WHn), 256, FA_BYTES>>>(qkv, attn, shifted);

        // output projection
        gemm_tc<<<dim3(Dd / 128, NTOK / 128), 256>>>(
            attn, Dd, Wo + (size_t)i * Dd * Dd, Dd,
            bo + (size_t)i * Dd, tmp, Dd, Dd, 0);

        // residual + LN1, scatter back (inverse roll)
        add_ln<<<NTOK, 256>>>(xw, tmp, ln1s + (size_t)i * Dd, ln1b + (size_t)i * Dd,
                              x, 1, shift);

        // FFN
        gemm_tc<<<dim3(DFFd / 128, NTOK / 128), 256>>>(
            x, Dd, W1 + (size_t)i * DFFd * Dd, Dd,
            b1 + (size_t)i * DFFd, ffn, DFFd, Dd, 1);
        gemm_tc<<<dim3(Dd / 128, NTOK / 128), 256>>>(
            ffn, DFFd, W2 + (size_t)i * Dd * DFFd, DFFd,
            b2 + (size_t)i * Dd, tmp, Dd, DFFd, 0);

        // residual + LN2 (final layer writes straight to d_out)
        add_ln<<<NTOK, 256>>>(x, tmp, ln2s + (size_t)i * Dd, ln2b + (size_t)i * Dd,
                              (i == Ll - 1) ? out : x, 0, 0);
    }
    (void)in_sizes; (void)n_in; (void)out_size;
}